// round 1
// baseline (speedup 1.0000x reference)
#include <cuda_runtime.h>
#include <cuda_bf16.h>
#include <cstdint>

#define N_NODES 100000
#define N_EDGES 1600000
#define IN_F    512
#define HID_F   128
#define N_CLS   64

// ---------------- device scratch (no allocations allowed) ----------------
__device__ float g_h1[(size_t)N_NODES * HID_F];   // x@w1+b1
__device__ float g_h2[(size_t)N_NODES * HID_F];   // relu(spmm(h1))
__device__ float g_h3[(size_t)N_NODES * N_CLS];   // h2@w2+b2
__device__ int   g_deg[N_NODES + 1];
__device__ int   g_rowptr[N_NODES + 1];
__device__ int   g_fill[N_NODES];
__device__ int   g_scol[N_EDGES];
__device__ float g_sval[N_EDGES];

// ---------------- CSR build ----------------
__global__ void zero_deg_kernel() {
    int i = blockIdx.x * blockDim.x + threadIdx.x;
    if (i <= N_NODES) g_deg[i] = 0;
}

__global__ void count_kernel(const int* __restrict__ row) {
    int e = blockIdx.x * blockDim.x + threadIdx.x;
    if (e < N_EDGES) atomicAdd(&g_deg[row[e]], 1);
}

__global__ void scan_kernel() {
    __shared__ int partial[1024];
    int t = threadIdx.x;
    const int CH = (N_NODES + 1023) / 1024;  // 98
    int base = t * CH;
    int s = 0;
    for (int j = 0; j < CH; j++) {
        int i = base + j;
        if (i < N_NODES) s += g_deg[i];
    }
    partial[t] = s;
    __syncthreads();
    if (t == 0) {
        int run = 0;
        for (int i = 0; i < 1024; i++) { int v = partial[i]; partial[i] = run; run += v; }
    }
    __syncthreads();
    int run = partial[t];
    for (int j = 0; j < CH; j++) {
        int i = base + j;
        if (i < N_NODES) {
            g_rowptr[i] = run;
            g_fill[i]   = run;
            run += g_deg[i];
        }
    }
    if (t == 0) g_rowptr[N_NODES] = N_EDGES;
}

__global__ void scatter_kernel(const int* __restrict__ row,
                               const int* __restrict__ col,
                               const float* __restrict__ val) {
    int e = blockIdx.x * blockDim.x + threadIdx.x;
    if (e < N_EDGES) {
        int r = row[e];
        int p = atomicAdd(&g_fill[r], 1);
        g_scol[p] = col[e];
        g_sval[p] = val[e];
    }
}

// ---------------- GEMM1: h1 = x @ w1 + b1   (100000x512 @ 512x128) ----------
// BM=64, BN=128, BK=16, 256 threads, each computes 8x4.
__global__ __launch_bounds__(256) void gemm1_kernel(
    const float* __restrict__ X, const float* __restrict__ W,
    const float* __restrict__ B, float* __restrict__ O) {
    __shared__ float As[16][64];
    __shared__ float Bs[16][128];
    int t = threadIdx.x;
    int row0 = blockIdx.x * 64;

    int tn = t & 31, tm = t >> 5;
    int n0 = tn * 4, m0 = tm * 8;

    int am = t >> 2;
    int ak = (t & 3) * 4;
    int bkr = t >> 5;           // 0..7
    int bn  = (t & 31) * 4;

    float acc[8][4];
#pragma unroll
    for (int r = 0; r < 8; r++)
#pragma unroll
        for (int c = 0; c < 4; c++) acc[r][c] = 0.f;

    for (int k0 = 0; k0 < IN_F; k0 += 16) {
        float4 av = make_float4(0.f, 0.f, 0.f, 0.f);
        int gr = row0 + am;
        if (gr < N_NODES)
            av = *(const float4*)&X[(size_t)gr * IN_F + k0 + ak];
        As[ak + 0][am] = av.x;
        As[ak + 1][am] = av.y;
        As[ak + 2][am] = av.z;
        As[ak + 3][am] = av.w;

        *(float4*)&Bs[bkr][bn]     = *(const float4*)&W[(size_t)(k0 + bkr) * 128 + bn];
        *(float4*)&Bs[bkr + 8][bn] = *(const float4*)&W[(size_t)(k0 + bkr + 8) * 128 + bn];
        __syncthreads();

#pragma unroll
        for (int k = 0; k < 16; k++) {
            float4 b = *(float4*)&Bs[k][n0];
            float a[8];
#pragma unroll
            for (int r = 0; r < 8; r++) a[r] = As[k][m0 + r];
#pragma unroll
            for (int r = 0; r < 8; r++) {
                acc[r][0] += a[r] * b.x;
                acc[r][1] += a[r] * b.y;
                acc[r][2] += a[r] * b.z;
                acc[r][3] += a[r] * b.w;
            }
        }
        __syncthreads();
    }

    float4 bias = *(const float4*)&B[n0];
#pragma unroll
    for (int r = 0; r < 8; r++) {
        int gr = row0 + m0 + r;
        if (gr < N_NODES) {
            float4 o;
            o.x = acc[r][0] + bias.x;
            o.y = acc[r][1] + bias.y;
            o.z = acc[r][2] + bias.z;
            o.w = acc[r][3] + bias.w;
            *(float4*)&O[(size_t)gr * 128 + n0] = o;
        }
    }
}

// ---------------- GEMM2: h3 = h2 @ w2 + b2  (100000x128 @ 128x64) -----------
// BM=64, BN=64, BK=16, 256 threads, each computes 4x4.
__global__ __launch_bounds__(256) void gemm2_kernel(
    const float* __restrict__ X, const float* __restrict__ W,
    const float* __restrict__ B, float* __restrict__ O) {
    __shared__ float As[16][64];
    __shared__ float Bs[16][64];
    int t = threadIdx.x;
    int row0 = blockIdx.x * 64;

    int tn = t & 15, tm = t >> 4;
    int n0 = tn * 4, m0 = tm * 4;

    int am = t >> 2;
    int ak = (t & 3) * 4;
    int bkr = t >> 4;          // 0..15
    int bn  = (t & 15) * 4;

    float acc[4][4];
#pragma unroll
    for (int r = 0; r < 4; r++)
#pragma unroll
        for (int c = 0; c < 4; c++) acc[r][c] = 0.f;

    for (int k0 = 0; k0 < HID_F; k0 += 16) {
        float4 av = make_float4(0.f, 0.f, 0.f, 0.f);
        int gr = row0 + am;
        if (gr < N_NODES)
            av = *(const float4*)&X[(size_t)gr * HID_F + k0 + ak];
        As[ak + 0][am] = av.x;
        As[ak + 1][am] = av.y;
        As[ak + 2][am] = av.z;
        As[ak + 3][am] = av.w;

        *(float4*)&Bs[bkr][bn] = *(const float4*)&W[(size_t)(k0 + bkr) * 64 + bn];
        __syncthreads();

#pragma unroll
        for (int k = 0; k < 16; k++) {
            float4 b = *(float4*)&Bs[k][n0];
            float a[4];
#pragma unroll
            for (int r = 0; r < 4; r++) a[r] = As[k][m0 + r];
#pragma unroll
            for (int r = 0; r < 4; r++) {
                acc[r][0] += a[r] * b.x;
                acc[r][1] += a[r] * b.y;
                acc[r][2] += a[r] * b.z;
                acc[r][3] += a[r] * b.w;
            }
        }
        __syncthreads();
    }

    float4 bias = *(const float4*)&B[n0];
#pragma unroll
    for (int r = 0; r < 4; r++) {
        int gr = row0 + m0 + r;
        if (gr < N_NODES) {
            float4 o;
            o.x = acc[r][0] + bias.x;
            o.y = acc[r][1] + bias.y;
            o.z = acc[r][2] + bias.z;
            o.w = acc[r][3] + bias.w;
            *(float4*)&O[(size_t)gr * 64 + n0] = o;
        }
    }
}

// ---------------- SpMM (CSR, row-owned, no atomics) ----------------
// h2[i][f] = relu( sum_e val[e] * h1[col[e]][f] )
__global__ __launch_bounds__(HID_F) void spmm1_kernel(
    const float* __restrict__ h1, float* __restrict__ h2) {
    int i = blockIdx.x;
    int f = threadIdx.x;
    int s = g_rowptr[i], e = g_rowptr[i + 1];
    float acc0 = 0.f, acc1 = 0.f;
    int j = s;
    for (; j + 1 < e; j += 2) {
        int   c0 = g_scol[j],     c1 = g_scol[j + 1];
        float v0 = g_sval[j],     v1 = g_sval[j + 1];
        acc0 += v0 * h1[(size_t)c0 * HID_F + f];
        acc1 += v1 * h1[(size_t)c1 * HID_F + f];
    }
    if (j < e) {
        int c = g_scol[j];
        acc0 += g_sval[j] * h1[(size_t)c * HID_F + f];
    }
    h2[(size_t)i * HID_F + f] = fmaxf(acc0 + acc1, 0.f);
}

// out[i][f] = sum_e val[e] * h3[col[e]][f]
__global__ __launch_bounds__(N_CLS) void spmm2_kernel(
    const float* __restrict__ h3, float* __restrict__ out) {
    int i = blockIdx.x;
    int f = threadIdx.x;
    int s = g_rowptr[i], e = g_rowptr[i + 1];
    float acc0 = 0.f, acc1 = 0.f;
    int j = s;
    for (; j + 1 < e; j += 2) {
        int   c0 = g_scol[j],     c1 = g_scol[j + 1];
        float v0 = g_sval[j],     v1 = g_sval[j + 1];
        acc0 += v0 * h3[(size_t)c0 * N_CLS + f];
        acc1 += v1 * h3[(size_t)c1 * N_CLS + f];
    }
    if (j < e) {
        int c = g_scol[j];
        acc0 += g_sval[j] * h3[(size_t)c * N_CLS + f];
    }
    out[(size_t)i * N_CLS + f] = acc0 + acc1;
}

// ---------------- launch ----------------
extern "C" void kernel_launch(void* const* d_in, const int* in_sizes, int n_in,
                              void* d_out, int out_size) {
    const float* x       = (const float*)d_in[0];
    const int*   adj_row = (const int*)d_in[1];
    const int*   adj_col = (const int*)d_in[2];
    const float* adj_val = (const float*)d_in[3];
    const float* w1      = (const float*)d_in[4];
    const float* b1      = (const float*)d_in[5];
    const float* w2      = (const float*)d_in[6];
    const float* b2      = (const float*)d_in[7];
    float* out = (float*)d_out;

    float* h1 = nullptr; float* h2 = nullptr; float* h3 = nullptr;
    cudaGetSymbolAddress((void**)&h1, g_h1);
    cudaGetSymbolAddress((void**)&h2, g_h2);
    cudaGetSymbolAddress((void**)&h3, g_h3);

    // CSR build
    zero_deg_kernel<<<(N_NODES + 256) / 256, 256>>>();
    count_kernel<<<(N_EDGES + 255) / 256, 256>>>(adj_row);
    scan_kernel<<<1, 1024>>>();
    scatter_kernel<<<(N_EDGES + 255) / 256, 256>>>(adj_row, adj_col, adj_val);

    // Layer 1
    gemm1_kernel<<<(N_NODES + 63) / 64, 256>>>(x, w1, b1, h1);
    spmm1_kernel<<<N_NODES, HID_F>>>(h1, h2);

    // Layer 2
    gemm2_kernel<<<(N_NODES + 63) / 64, 256>>>(h2, w2, b2, h3);
    spmm2_kernel<<<N_NODES, N_CLS>>>(h3, out);
}

// round 3
// speedup vs baseline: 1.1620x; 1.1620x over previous
#include <cuda_runtime.h>
#include <cuda_bf16.h>
#include <cstdint>

#define N_NODES 100000
#define N_EDGES 1600000
#define IN_F    512
#define HID_F   128
#define N_CLS   64

// ---------------- device scratch (no allocations allowed) ----------------
__device__ float g_h1[(size_t)N_NODES * HID_F];   // x@w1+b1
__device__ float g_h2[(size_t)N_NODES * HID_F];   // relu(spmm(h1))
__device__ float g_h3[(size_t)N_NODES * N_CLS];   // h2@w2+b2
__device__ int   g_deg[N_NODES + 1];
__device__ int   g_rowptr[N_NODES + 1];
__device__ int   g_fill[N_NODES];
__device__ int   g_scol[N_EDGES];
__device__ float g_sval[N_EDGES];
// transposed, bf16-split weights (K-contiguous rows)
__device__ __align__(16) __nv_bfloat16 g_w1t_hi[HID_F * IN_F];   // [128][512]
__device__ __align__(16) __nv_bfloat16 g_w1t_lo[HID_F * IN_F];
__device__ __align__(16) __nv_bfloat16 g_w2t_hi[N_CLS * HID_F];  // [64][128]
__device__ __align__(16) __nv_bfloat16 g_w2t_lo[N_CLS * HID_F];

// ---------------- CSR build ----------------
__global__ void zero_deg_kernel() {
    int i = blockIdx.x * blockDim.x + threadIdx.x;
    if (i <= N_NODES) g_deg[i] = 0;
}
__global__ void count_kernel(const int* __restrict__ row) {
    int e = blockIdx.x * blockDim.x + threadIdx.x;
    if (e < N_EDGES) atomicAdd(&g_deg[row[e]], 1);
}
__global__ void scan_kernel() {
    __shared__ int partial[1024];
    int t = threadIdx.x;
    const int CH = (N_NODES + 1023) / 1024;
    int base = t * CH;
    int s = 0;
    for (int j = 0; j < CH; j++) { int i = base + j; if (i < N_NODES) s += g_deg[i]; }
    partial[t] = s;
    __syncthreads();
    if (t == 0) {
        int run = 0;
        for (int i = 0; i < 1024; i++) { int v = partial[i]; partial[i] = run; run += v; }
    }
    __syncthreads();
    int run = partial[t];
    for (int j = 0; j < CH; j++) {
        int i = base + j;
        if (i < N_NODES) { g_rowptr[i] = run; g_fill[i] = run; run += g_deg[i]; }
    }
    if (t == 0) g_rowptr[N_NODES] = N_EDGES;
}
__global__ void scatter_kernel(const int* __restrict__ row, const int* __restrict__ col,
                               const float* __restrict__ val) {
    int e = blockIdx.x * blockDim.x + threadIdx.x;
    if (e < N_EDGES) {
        int r = row[e];
        int p = atomicAdd(&g_fill[r], 1);
        g_scol[p] = col[e];
        g_sval[p] = val[e];
    }
}

// ---------------- weight prep: transpose + bf16 hi/lo split ----------------
__global__ void prep_w1t_kernel(const float* __restrict__ w1) {
    int idx = blockIdx.x * blockDim.x + threadIdx.x;
    if (idx < IN_F * HID_F) {
        int k = idx >> 7, n = idx & 127;   // w1[k][n], n-stride 128
        float v = w1[idx];
        __nv_bfloat16 h = __float2bfloat16(v);
        float r = v - __bfloat162float(h);
        g_w1t_hi[n * IN_F + k] = h;
        g_w1t_lo[n * IN_F + k] = __float2bfloat16(r);
    }
}
__global__ void prep_w2t_kernel(const float* __restrict__ w2) {
    int idx = blockIdx.x * blockDim.x + threadIdx.x;
    if (idx < HID_F * N_CLS) {
        int k = idx >> 6, n = idx & 63;    // w2[k][n], n-stride 64
        float v = w2[idx];
        __nv_bfloat16 h = __float2bfloat16(v);
        float r = v - __bfloat162float(h);
        g_w2t_hi[n * HID_F + k] = h;
        g_w2t_lo[n * HID_F + k] = __float2bfloat16(r);
    }
}

// ---------------- mma.sync bf16 GEMM (fp32-accurate via hi/lo split) --------
// C[M,BN] = A[M,K] @ W[K,BN] + bias, with Wt = W^T pre-split into bf16 hi/lo.
// CTA tile: 128 x BN. 8 warps: warp_m = wid&3 (32 rows), warp_n = wid>>2.
// BK=64 chunk, K-contiguous smem rows, LDK=BK+8 pad -> conflict-free frag LDS.
#define BK  64
#define LDK 72

__device__ __forceinline__ void mma_bf16(float* c, const uint32_t* a, const uint32_t* b) {
    asm volatile(
        "mma.sync.aligned.m16n8k16.row.col.f32.bf16.bf16.f32 "
        "{%0,%1,%2,%3}, {%4,%5,%6,%7}, {%8,%9}, {%0,%1,%2,%3};"
        : "+f"(c[0]), "+f"(c[1]), "+f"(c[2]), "+f"(c[3])
        : "r"(a[0]), "r"(a[1]), "r"(a[2]), "r"(a[3]), "r"(b[0]), "r"(b[1]));
}

__device__ __forceinline__ uint32_t pack_bf16x2(__nv_bfloat16 a, __nv_bfloat16 b) {
    __nv_bfloat162 p; p.x = a; p.y = b;
    return *reinterpret_cast<uint32_t*>(&p);
}

template <int BN, int K_TOTAL, bool RELU_IN>  // RELU_IN unused; kept for shape
__global__ __launch_bounds__(256) void gemm_mma_kernel(
    const float* __restrict__ X,
    const __nv_bfloat16* __restrict__ Wt_hi,
    const __nv_bfloat16* __restrict__ Wt_lo,
    const float* __restrict__ Bias,
    float* __restrict__ O) {
    extern __shared__ char smraw[];
    __nv_bfloat16* As_hi = (__nv_bfloat16*)smraw;                 // [128][LDK]
    __nv_bfloat16* As_lo = As_hi + 128 * LDK;
    __nv_bfloat16* Bs_hi = As_lo + 128 * LDK;                     // [BN][LDK]
    __nv_bfloat16* Bs_lo = Bs_hi + BN * LDK;

    const int t = threadIdx.x;
    const int lane = t & 31;
    const int wid = t >> 5;
    const int warp_m = wid & 3;          // 4 M-warps x 32 rows
    const int warp_n = wid >> 2;         // 2 N-warps
    const int NT = BN / 16;              // n-tiles (8 cols each) per warp
    const int n0 = warp_n * (BN / 2);
    const int row0 = blockIdx.x * 128;

    float acc[2][BN / 16][4];
#pragma unroll
    for (int mt = 0; mt < 2; mt++)
#pragma unroll
        for (int nt = 0; nt < NT; nt++)
#pragma unroll
            for (int i = 0; i < 4; i++) acc[mt][nt][i] = 0.f;

    const int gq = lane >> 2;            // 0..7
    const int gc2 = (lane & 3) * 2;      // even col/k offset

    for (int c = 0; c < K_TOTAL / BK; c++) {
        const int k0 = c * BK;
        // ---- load A chunk: 128 rows x 64 fp32 -> split hi/lo bf16 ----
#pragma unroll
        for (int idx = t; idx < 128 * 16; idx += 256) {
            int row = idx >> 4;
            int col = (idx & 15) * 4;
            int gr = row0 + row;
            if (gr >= N_NODES) gr = N_NODES - 1;
            float4 v = *(const float4*)&X[(size_t)gr * K_TOTAL + k0 + col];
            __nv_bfloat16 h0 = __float2bfloat16(v.x);
            __nv_bfloat16 h1 = __float2bfloat16(v.y);
            __nv_bfloat16 h2 = __float2bfloat16(v.z);
            __nv_bfloat16 h3 = __float2bfloat16(v.w);
            uint2 hi, lo;
            hi.x = pack_bf16x2(h0, h1);
            hi.y = pack_bf16x2(h2, h3);
            lo.x = pack_bf16x2(__float2bfloat16(v.x - __bfloat162float(h0)),
                               __float2bfloat16(v.y - __bfloat162float(h1)));
            lo.y = pack_bf16x2(__float2bfloat16(v.z - __bfloat162float(h2)),
                               __float2bfloat16(v.w - __bfloat162float(h3)));
            *(uint2*)&As_hi[row * LDK + col] = hi;
            *(uint2*)&As_lo[row * LDK + col] = lo;
        }
        // ---- load B chunk: BN rows x 64 bf16 (hi & lo), plain copies ----
#pragma unroll
        for (int idx = t; idx < BN * 8; idx += 256) {
            int row = idx >> 3;
            int q = (idx & 7) * 8;
            *(uint4*)&Bs_hi[row * LDK + q] = *(const uint4*)&Wt_hi[(size_t)row * K_TOTAL + k0 + q];
            *(uint4*)&Bs_lo[row * LDK + q] = *(const uint4*)&Wt_lo[(size_t)row * K_TOTAL + k0 + q];
        }
        __syncthreads();

        // ---- compute: 4 k16 steps, 3 products each ----
#pragma unroll
        for (int ks = 0; ks < 4; ks++) {
            const int k = ks * 16;
            uint32_t ah[2][4], al[2][4];
#pragma unroll
            for (int mt = 0; mt < 2; mt++) {
                const int rb = warp_m * 32 + mt * 16 + gq;
                const __nv_bfloat16* ph = &As_hi[rb * LDK + k + gc2];
                const __nv_bfloat16* pl = &As_lo[rb * LDK + k + gc2];
                ah[mt][0] = *(const uint32_t*)(ph);
                ah[mt][1] = *(const uint32_t*)(ph + 8 * LDK);
                ah[mt][2] = *(const uint32_t*)(ph + 8);
                ah[mt][3] = *(const uint32_t*)(ph + 8 * LDK + 8);
                al[mt][0] = *(const uint32_t*)(pl);
                al[mt][1] = *(const uint32_t*)(pl + 8 * LDK);
                al[mt][2] = *(const uint32_t*)(pl + 8);
                al[mt][3] = *(const uint32_t*)(pl + 8 * LDK + 8);
            }
#pragma unroll
            for (int nt = 0; nt < NT; nt++) {
                const int nrow = n0 + nt * 8 + gq;
                const __nv_bfloat16* ph = &Bs_hi[nrow * LDK + k + gc2];
                const __nv_bfloat16* pl = &Bs_lo[nrow * LDK + k + gc2];
                uint32_t bh[2], bl[2];
                bh[0] = *(const uint32_t*)(ph);
                bh[1] = *(const uint32_t*)(ph + 8);
                bl[0] = *(const uint32_t*)(pl);
                bl[1] = *(const uint32_t*)(pl + 8);
#pragma unroll
                for (int mt = 0; mt < 2; mt++) {
                    mma_bf16(acc[mt][nt], ah[mt], bh);
                    mma_bf16(acc[mt][nt], ah[mt], bl);
                    mma_bf16(acc[mt][nt], al[mt], bh);
                }
            }
        }
        __syncthreads();
    }

    // ---- epilogue: bias + store ----
#pragma unroll
    for (int nt = 0; nt < NT; nt++) {
        const int colb = n0 + nt * 8 + gc2;
        float2 bb = *(const float2*)&Bias[colb];
#pragma unroll
        for (int mt = 0; mt < 2; mt++) {
            int r0 = row0 + warp_m * 32 + mt * 16 + gq;
            if (r0 < N_NODES) {
                float2 o0;
                o0.x = acc[mt][nt][0] + bb.x;
                o0.y = acc[mt][nt][1] + bb.y;
                *(float2*)&O[(size_t)r0 * BN + colb] = o0;
            }
            int r1 = r0 + 8;
            if (r1 < N_NODES) {
                float2 o1;
                o1.x = acc[mt][nt][2] + bb.x;
                o1.y = acc[mt][nt][3] + bb.y;
                *(float2*)&O[(size_t)r1 * BN + colb] = o1;
            }
        }
    }
}

// ---------------- SpMM (CSR, row-owned, no atomics) ----------------
__global__ __launch_bounds__(HID_F) void spmm1_kernel(
    const float* __restrict__ h1, float* __restrict__ h2) {
    int i = blockIdx.x;
    int f = threadIdx.x;
    int s = g_rowptr[i], e = g_rowptr[i + 1];
    float acc0 = 0.f, acc1 = 0.f;
    int j = s;
    for (; j + 1 < e; j += 2) {
        int c0 = g_scol[j], c1 = g_scol[j + 1];
        float v0 = g_sval[j], v1 = g_sval[j + 1];
        acc0 += v0 * h1[(size_t)c0 * HID_F + f];
        acc1 += v1 * h1[(size_t)c1 * HID_F + f];
    }
    if (j < e) {
        int c = g_scol[j];
        acc0 += g_sval[j] * h1[(size_t)c * HID_F + f];
    }
    h2[(size_t)i * HID_F + f] = fmaxf(acc0 + acc1, 0.f);
}

__global__ __launch_bounds__(N_CLS) void spmm2_kernel(
    const float* __restrict__ h3, float* __restrict__ out) {
    int i = blockIdx.x;
    int f = threadIdx.x;
    int s = g_rowptr[i], e = g_rowptr[i + 1];
    float acc0 = 0.f, acc1 = 0.f;
    int j = s;
    for (; j + 1 < e; j += 2) {
        int c0 = g_scol[j], c1 = g_scol[j + 1];
        float v0 = g_sval[j], v1 = g_sval[j + 1];
        acc0 += v0 * h3[(size_t)c0 * N_CLS + f];
        acc1 += v1 * h3[(size_t)c1 * N_CLS + f];
    }
    if (j < e) {
        int c = g_scol[j];
        acc0 += g_sval[j] * h3[(size_t)c * N_CLS + f];
    }
    out[(size_t)i * N_CLS + f] = acc0 + acc1;
}

// ---------------- launch ----------------
#define SMEM_G1 ((2 * 128 + 2 * HID_F) * LDK * 2)   // 73728
#define SMEM_G2 ((2 * 128 + 2 * N_CLS) * LDK * 2)   // 55296

extern "C" void kernel_launch(void* const* d_in, const int* in_sizes, int n_in,
                              void* d_out, int out_size) {
    const float* x       = (const float*)d_in[0];
    const int*   adj_row = (const int*)d_in[1];
    const int*   adj_col = (const int*)d_in[2];
    const float* adj_val = (const float*)d_in[3];
    const float* w1      = (const float*)d_in[4];
    const float* b1      = (const float*)d_in[5];
    const float* w2      = (const float*)d_in[6];
    const float* b2      = (const float*)d_in[7];
    float* out = (float*)d_out;

    float* h1 = nullptr; float* h2 = nullptr; float* h3 = nullptr;
    const __nv_bfloat16 *w1h, *w1l, *w2h, *w2l;
    cudaGetSymbolAddress((void**)&h1, g_h1);
    cudaGetSymbolAddress((void**)&h2, g_h2);
    cudaGetSymbolAddress((void**)&h3, g_h3);
    cudaGetSymbolAddress((void**)&w1h, g_w1t_hi);
    cudaGetSymbolAddress((void**)&w1l, g_w1t_lo);
    cudaGetSymbolAddress((void**)&w2h, g_w2t_hi);
    cudaGetSymbolAddress((void**)&w2l, g_w2t_lo);

    static bool attr_done = false;
    if (!attr_done) {
        cudaFuncSetAttribute(gemm_mma_kernel<HID_F, IN_F, false>,
                             cudaFuncAttributeMaxDynamicSharedMemorySize, SMEM_G1);
        cudaFuncSetAttribute(gemm_mma_kernel<N_CLS, HID_F, false>,
                             cudaFuncAttributeMaxDynamicSharedMemorySize, SMEM_G2);
        attr_done = true;
    }

    // CSR build + weight prep
    zero_deg_kernel<<<(N_NODES + 256) / 256, 256>>>();
    count_kernel<<<(N_EDGES + 255) / 256, 256>>>(adj_row);
    scan_kernel<<<1, 1024>>>();
    scatter_kernel<<<(N_EDGES + 255) / 256, 256>>>(adj_row, adj_col, adj_val);
    prep_w1t_kernel<<<(IN_F * HID_F + 255) / 256, 256>>>(w1);
    prep_w2t_kernel<<<(HID_F * N_CLS + 255) / 256, 256>>>(w2);

    // Layer 1
    gemm_mma_kernel<HID_F, IN_F, false>
        <<<(N_NODES + 127) / 128, 256, SMEM_G1>>>(x, w1h, w1l, b1, h1);
    spmm1_kernel<<<N_NODES, HID_F>>>(h1, h2);

    // Layer 2
    gemm_mma_kernel<N_CLS, HID_F, false>
        <<<(N_NODES + 127) / 128, 256, SMEM_G2>>>(h2, w2h, w2l, b2, h3);
    spmm2_kernel<<<N_NODES, N_CLS>>>(h3, out);
}

// round 4
// speedup vs baseline: 1.3197x; 1.1357x over previous
#include <cuda_runtime.h>
#include <cuda_bf16.h>
#include <cstdint>

#define N_NODES 100000
#define N_EDGES 1600000
#define IN_F    512
#define HID_F   128
#define N_CLS   64

// ---------------- device scratch (no allocations allowed) ----------------
__device__ float g_h1[(size_t)N_NODES * HID_F];   // x@w1+b1
__device__ float g_h2[(size_t)N_NODES * HID_F];   // relu(spmm(h1))
__device__ float g_h3[(size_t)N_NODES * N_CLS];   // h2@w2+b2
__device__ int   g_deg[N_NODES + 1];
__device__ int   g_rowptr[N_NODES + 1];
__device__ int   g_fill[N_NODES];
__device__ int   g_scol[N_EDGES];
__device__ float g_sval[N_EDGES];
// transposed, bf16-split weights (K-contiguous rows)
__device__ __align__(16) __nv_bfloat16 g_w1t_hi[HID_F * IN_F];   // [128][512]
__device__ __align__(16) __nv_bfloat16 g_w1t_lo[HID_F * IN_F];
__device__ __align__(16) __nv_bfloat16 g_w2t_hi[N_CLS * HID_F];  // [64][128]
__device__ __align__(16) __nv_bfloat16 g_w2t_lo[N_CLS * HID_F];

// ---------------- CSR build ----------------
__global__ void zero_deg_kernel() {
    int i = blockIdx.x * blockDim.x + threadIdx.x;
    if (i <= N_NODES) g_deg[i] = 0;
}
__global__ void count_kernel(const int* __restrict__ row) {
    int e = blockIdx.x * blockDim.x + threadIdx.x;
    if (e < N_EDGES) atomicAdd(&g_deg[row[e]], 1);
}
// single-block scan, shuffle-based (no serial 1024-loop)
__global__ __launch_bounds__(1024) void scan_kernel() {
    __shared__ int wsum[32];
    int t = threadIdx.x;
    const int CH = (N_NODES + 1023) / 1024;  // 98
    int base = t * CH;
    int s = 0;
#pragma unroll 4
    for (int j = 0; j < CH; j++) {
        int i = base + j;
        if (i < N_NODES) s += g_deg[i];
    }
    // warp inclusive scan of s
    int lane = t & 31, wid = t >> 5;
    int v = s;
#pragma unroll
    for (int d = 1; d < 32; d <<= 1) {
        int n = __shfl_up_sync(0xFFFFFFFF, v, d);
        if (lane >= d) v += n;
    }
    if (lane == 31) wsum[wid] = v;
    __syncthreads();
    if (wid == 0) {
        int w = (lane < 32) ? wsum[lane] : 0;
#pragma unroll
        for (int d = 1; d < 32; d <<= 1) {
            int n = __shfl_up_sync(0xFFFFFFFF, w, d);
            if (lane >= d) w += n;
        }
        wsum[lane] = w;
    }
    __syncthreads();
    int excl = v - s + (wid ? wsum[wid - 1] : 0);   // exclusive prefix for this thread
    int run = excl;
    for (int j = 0; j < CH; j++) {
        int i = base + j;
        if (i < N_NODES) {
            int d = g_deg[i];
            g_rowptr[i] = run;
            g_fill[i]   = run;
            run += d;
        }
    }
    if (t == 1023) g_rowptr[N_NODES] = N_EDGES;
}
__global__ void scatter_kernel(const int* __restrict__ row, const int* __restrict__ col,
                               const float* __restrict__ val) {
    int e = blockIdx.x * blockDim.x + threadIdx.x;
    if (e < N_EDGES) {
        int r = row[e];
        int p = atomicAdd(&g_fill[r], 1);
        g_scol[p] = col[e];
        g_sval[p] = val[e];
    }
}

// ---------------- weight prep: transpose + bf16 hi/lo split ----------------
__global__ void prep_w1t_kernel(const float* __restrict__ w1) {
    int idx = blockIdx.x * blockDim.x + threadIdx.x;
    if (idx < IN_F * HID_F) {
        int k = idx >> 7, n = idx & 127;
        float v = w1[idx];
        __nv_bfloat16 h = __float2bfloat16(v);
        float r = v - __bfloat162float(h);
        g_w1t_hi[n * IN_F + k] = h;
        g_w1t_lo[n * IN_F + k] = __float2bfloat16(r);
    }
}
__global__ void prep_w2t_kernel(const float* __restrict__ w2) {
    int idx = blockIdx.x * blockDim.x + threadIdx.x;
    if (idx < HID_F * N_CLS) {
        int k = idx >> 6, n = idx & 63;
        float v = w2[idx];
        __nv_bfloat16 h = __float2bfloat16(v);
        float r = v - __bfloat162float(h);
        g_w2t_hi[n * HID_F + k] = h;
        g_w2t_lo[n * HID_F + k] = __float2bfloat16(r);
    }
}

// ---------------- mma.sync bf16 GEMM (fp32-accurate via hi/lo split) --------
#define BK  64
#define LDK 72

__device__ __forceinline__ void mma_bf16(float* c, const uint32_t* a, const uint32_t* b) {
    asm volatile(
        "mma.sync.aligned.m16n8k16.row.col.f32.bf16.bf16.f32 "
        "{%0,%1,%2,%3}, {%4,%5,%6,%7}, {%8,%9}, {%0,%1,%2,%3};"
        : "+f"(c[0]), "+f"(c[1]), "+f"(c[2]), "+f"(c[3])
        : "r"(a[0]), "r"(a[1]), "r"(a[2]), "r"(a[3]), "r"(b[0]), "r"(b[1]));
}

__device__ __forceinline__ uint32_t pack_bf16x2(__nv_bfloat16 a, __nv_bfloat16 b) {
    __nv_bfloat162 p; p.x = a; p.y = b;
    return *reinterpret_cast<uint32_t*>(&p);
}

template <int BN, int K_TOTAL>
__global__ __launch_bounds__(256) void gemm_mma_kernel(
    const float* __restrict__ X,
    const __nv_bfloat16* __restrict__ Wt_hi,
    const __nv_bfloat16* __restrict__ Wt_lo,
    const float* __restrict__ Bias,
    float* __restrict__ O) {
    extern __shared__ char smraw[];
    __nv_bfloat16* As_hi = (__nv_bfloat16*)smraw;                 // [128][LDK]
    __nv_bfloat16* As_lo = As_hi + 128 * LDK;
    __nv_bfloat16* Bs_hi = As_lo + 128 * LDK;                     // [BN][LDK]
    __nv_bfloat16* Bs_lo = Bs_hi + BN * LDK;

    const int t = threadIdx.x;
    const int lane = t & 31;
    const int wid = t >> 5;
    const int warp_m = wid & 3;
    const int warp_n = wid >> 2;
    const int NT = BN / 16;
    const int n0 = warp_n * (BN / 2);
    const int row0 = blockIdx.x * 128;

    float acc[2][BN / 16][4];
#pragma unroll
    for (int mt = 0; mt < 2; mt++)
#pragma unroll
        for (int nt = 0; nt < NT; nt++)
#pragma unroll
            for (int i = 0; i < 4; i++) acc[mt][nt][i] = 0.f;

    const int gq = lane >> 2;
    const int gc2 = (lane & 3) * 2;

    for (int c = 0; c < K_TOTAL / BK; c++) {
        const int k0 = c * BK;
#pragma unroll
        for (int idx = t; idx < 128 * 16; idx += 256) {
            int row = idx >> 4;
            int col = (idx & 15) * 4;
            int gr = row0 + row;
            if (gr >= N_NODES) gr = N_NODES - 1;
            float4 v = *(const float4*)&X[(size_t)gr * K_TOTAL + k0 + col];
            __nv_bfloat16 h0 = __float2bfloat16(v.x);
            __nv_bfloat16 h1 = __float2bfloat16(v.y);
            __nv_bfloat16 h2 = __float2bfloat16(v.z);
            __nv_bfloat16 h3 = __float2bfloat16(v.w);
            uint2 hi, lo;
            hi.x = pack_bf16x2(h0, h1);
            hi.y = pack_bf16x2(h2, h3);
            lo.x = pack_bf16x2(__float2bfloat16(v.x - __bfloat162float(h0)),
                               __float2bfloat16(v.y - __bfloat162float(h1)));
            lo.y = pack_bf16x2(__float2bfloat16(v.z - __bfloat162float(h2)),
                               __float2bfloat16(v.w - __bfloat162float(h3)));
            *(uint2*)&As_hi[row * LDK + col] = hi;
            *(uint2*)&As_lo[row * LDK + col] = lo;
        }
#pragma unroll
        for (int idx = t; idx < BN * 8; idx += 256) {
            int row = idx >> 3;
            int q = (idx & 7) * 8;
            *(uint4*)&Bs_hi[row * LDK + q] = *(const uint4*)&Wt_hi[(size_t)row * K_TOTAL + k0 + q];
            *(uint4*)&Bs_lo[row * LDK + q] = *(const uint4*)&Wt_lo[(size_t)row * K_TOTAL + k0 + q];
        }
        __syncthreads();

#pragma unroll
        for (int ks = 0; ks < 4; ks++) {
            const int k = ks * 16;
            uint32_t ah[2][4], al[2][4];
#pragma unroll
            for (int mt = 0; mt < 2; mt++) {
                const int rb = warp_m * 32 + mt * 16 + gq;
                const __nv_bfloat16* ph = &As_hi[rb * LDK + k + gc2];
                const __nv_bfloat16* pl = &As_lo[rb * LDK + k + gc2];
                ah[mt][0] = *(const uint32_t*)(ph);
                ah[mt][1] = *(const uint32_t*)(ph + 8 * LDK);
                ah[mt][2] = *(const uint32_t*)(ph + 8);
                ah[mt][3] = *(const uint32_t*)(ph + 8 * LDK + 8);
                al[mt][0] = *(const uint32_t*)(pl);
                al[mt][1] = *(const uint32_t*)(pl + 8 * LDK);
                al[mt][2] = *(const uint32_t*)(pl + 8);
                al[mt][3] = *(const uint32_t*)(pl + 8 * LDK + 8);
            }
#pragma unroll
            for (int nt = 0; nt < NT; nt++) {
                const int nrow = n0 + nt * 8 + gq;
                const __nv_bfloat16* ph = &Bs_hi[nrow * LDK + k + gc2];
                const __nv_bfloat16* pl = &Bs_lo[nrow * LDK + k + gc2];
                uint32_t bh[2], bl[2];
                bh[0] = *(const uint32_t*)(ph);
                bh[1] = *(const uint32_t*)(ph + 8);
                bl[0] = *(const uint32_t*)(pl);
                bl[1] = *(const uint32_t*)(pl + 8);
#pragma unroll
                for (int mt = 0; mt < 2; mt++) {
                    mma_bf16(acc[mt][nt], ah[mt], bh);
                    mma_bf16(acc[mt][nt], ah[mt], bl);
                    mma_bf16(acc[mt][nt], al[mt], bh);
                }
            }
        }
        __syncthreads();
    }

#pragma unroll
    for (int nt = 0; nt < NT; nt++) {
        const int colb = n0 + nt * 8 + gc2;
        float2 bb = *(const float2*)&Bias[colb];
#pragma unroll
        for (int mt = 0; mt < 2; mt++) {
            int r0 = row0 + warp_m * 32 + mt * 16 + gq;
            if (r0 < N_NODES) {
                float2 o0;
                o0.x = acc[mt][nt][0] + bb.x;
                o0.y = acc[mt][nt][1] + bb.y;
                *(float2*)&O[(size_t)r0 * BN + colb] = o0;
            }
            int r1 = r0 + 8;
            if (r1 < N_NODES) {
                float2 o1;
                o1.x = acc[mt][nt][2] + bb.x;
                o1.y = acc[mt][nt][3] + bb.y;
                *(float2*)&O[(size_t)r1 * BN + colb] = o1;
            }
        }
    }
}

// ---------------- SpMM: warp-per-node, 4-edge unroll, no atomics ------------
// Layer 1: F=128 floats -> one float4 per lane. ReLU on output.
__global__ __launch_bounds__(256) void spmm1_warp_kernel(
    const float* __restrict__ h1, float* __restrict__ h2) {
    int node = blockIdx.x * 8 + (threadIdx.x >> 5);
    int lane = threadIdx.x & 31;
    int s = g_rowptr[node], e = g_rowptr[node + 1];

    float4 a0 = make_float4(0.f, 0.f, 0.f, 0.f);
    float4 a1 = a0, a2 = a0, a3 = a0;
    const float4* H = (const float4*)h1;

    int j = s;
    for (; j + 3 < e; j += 4) {
        int   c0 = g_scol[j],     c1 = g_scol[j + 1];
        int   c2 = g_scol[j + 2], c3 = g_scol[j + 3];
        float v0 = g_sval[j],     v1 = g_sval[j + 1];
        float v2 = g_sval[j + 2], v3 = g_sval[j + 3];
        float4 x0 = H[(size_t)c0 * 32 + lane];
        float4 x1 = H[(size_t)c1 * 32 + lane];
        float4 x2 = H[(size_t)c2 * 32 + lane];
        float4 x3 = H[(size_t)c3 * 32 + lane];
        a0.x += v0 * x0.x; a0.y += v0 * x0.y; a0.z += v0 * x0.z; a0.w += v0 * x0.w;
        a1.x += v1 * x1.x; a1.y += v1 * x1.y; a1.z += v1 * x1.z; a1.w += v1 * x1.w;
        a2.x += v2 * x2.x; a2.y += v2 * x2.y; a2.z += v2 * x2.z; a2.w += v2 * x2.w;
        a3.x += v3 * x3.x; a3.y += v3 * x3.y; a3.z += v3 * x3.z; a3.w += v3 * x3.w;
    }
    for (; j < e; j++) {
        int c = g_scol[j];
        float v = g_sval[j];
        float4 x = H[(size_t)c * 32 + lane];
        a0.x += v * x.x; a0.y += v * x.y; a0.z += v * x.z; a0.w += v * x.w;
    }
    float4 o;
    o.x = fmaxf(a0.x + a1.x + a2.x + a3.x, 0.f);
    o.y = fmaxf(a0.y + a1.y + a2.y + a3.y, 0.f);
    o.z = fmaxf(a0.z + a1.z + a2.z + a3.z, 0.f);
    o.w = fmaxf(a0.w + a1.w + a2.w + a3.w, 0.f);
    ((float4*)h2)[(size_t)node * 32 + lane] = o;
}

// Layer 2: F=64 floats -> one float2 per lane.
__global__ __launch_bounds__(256) void spmm2_warp_kernel(
    const float* __restrict__ h3, float* __restrict__ out) {
    int node = blockIdx.x * 8 + (threadIdx.x >> 5);
    int lane = threadIdx.x & 31;
    int s = g_rowptr[node], e = g_rowptr[node + 1];

    float2 a0 = make_float2(0.f, 0.f);
    float2 a1 = a0, a2 = a0, a3 = a0;
    const float2* H = (const float2*)h3;

    int j = s;
    for (; j + 3 < e; j += 4) {
        int   c0 = g_scol[j],     c1 = g_scol[j + 1];
        int   c2 = g_scol[j + 2], c3 = g_scol[j + 3];
        float v0 = g_sval[j],     v1 = g_sval[j + 1];
        float v2 = g_sval[j + 2], v3 = g_sval[j + 3];
        float2 x0 = H[(size_t)c0 * 32 + lane];
        float2 x1 = H[(size_t)c1 * 32 + lane];
        float2 x2 = H[(size_t)c2 * 32 + lane];
        float2 x3 = H[(size_t)c3 * 32 + lane];
        a0.x += v0 * x0.x; a0.y += v0 * x0.y;
        a1.x += v1 * x1.x; a1.y += v1 * x1.y;
        a2.x += v2 * x2.x; a2.y += v2 * x2.y;
        a3.x += v3 * x3.x; a3.y += v3 * x3.y;
    }
    for (; j < e; j++) {
        int c = g_scol[j];
        float v = g_sval[j];
        float2 x = H[(size_t)c * 32 + lane];
        a0.x += v * x.x; a0.y += v * x.y;
    }
    float2 o;
    o.x = a0.x + a1.x + a2.x + a3.x;
    o.y = a0.y + a1.y + a2.y + a3.y;
    ((float2*)out)[(size_t)node * 32 + lane] = o;
}

// ---------------- launch ----------------
#define SMEM_G1 ((2 * 128 + 2 * HID_F) * LDK * 2)   // 73728
#define SMEM_G2 ((2 * 128 + 2 * N_CLS) * LDK * 2)   // 55296

extern "C" void kernel_launch(void* const* d_in, const int* in_sizes, int n_in,
                              void* d_out, int out_size) {
    const float* x       = (const float*)d_in[0];
    const int*   adj_row = (const int*)d_in[1];
    const int*   adj_col = (const int*)d_in[2];
    const float* adj_val = (const float*)d_in[3];
    const float* w1      = (const float*)d_in[4];
    const float* b1      = (const float*)d_in[5];
    const float* w2      = (const float*)d_in[6];
    const float* b2      = (const float*)d_in[7];
    float* out = (float*)d_out;

    float* h1 = nullptr; float* h2 = nullptr; float* h3 = nullptr;
    const __nv_bfloat16 *w1h, *w1l, *w2h, *w2l;
    cudaGetSymbolAddress((void**)&h1, g_h1);
    cudaGetSymbolAddress((void**)&h2, g_h2);
    cudaGetSymbolAddress((void**)&h3, g_h3);
    cudaGetSymbolAddress((void**)&w1h, g_w1t_hi);
    cudaGetSymbolAddress((void**)&w1l, g_w1t_lo);
    cudaGetSymbolAddress((void**)&w2h, g_w2t_hi);
    cudaGetSymbolAddress((void**)&w2l, g_w2t_lo);

    static bool attr_done = false;
    if (!attr_done) {
        cudaFuncSetAttribute(gemm_mma_kernel<HID_F, IN_F>,
                             cudaFuncAttributeMaxDynamicSharedMemorySize, SMEM_G1);
        cudaFuncSetAttribute(gemm_mma_kernel<N_CLS, HID_F>,
                             cudaFuncAttributeMaxDynamicSharedMemorySize, SMEM_G2);
        attr_done = true;
    }

    // CSR build + weight prep
    zero_deg_kernel<<<(N_NODES + 256) / 256, 256>>>();
    count_kernel<<<(N_EDGES + 255) / 256, 256>>>(adj_row);
    scan_kernel<<<1, 1024>>>();
    scatter_kernel<<<(N_EDGES + 255) / 256, 256>>>(adj_row, adj_col, adj_val);
    prep_w1t_kernel<<<(IN_F * HID_F + 255) / 256, 256>>>(w1);
    prep_w2t_kernel<<<(HID_F * N_CLS + 255) / 256, 256>>>(w2);

    // Layer 1
    gemm_mma_kernel<HID_F, IN_F>
        <<<(N_NODES + 127) / 128, 256, SMEM_G1>>>(x, w1h, w1l, b1, h1);
    spmm1_warp_kernel<<<(N_NODES + 7) / 8, 256>>>(h1, h2);

    // Layer 2
    gemm_mma_kernel<N_CLS, HID_F>
        <<<(N_NODES + 127) / 128, 256, SMEM_G2>>>(h2, w2h, w2l, b2, h3);
    spmm2_warp_kernel<<<(N_NODES + 7) / 8, 256>>>(h3, out);
}

// round 5
// speedup vs baseline: 1.8184x; 1.3779x over previous
#include <cuda_runtime.h>
#include <cuda_bf16.h>
#include <cstdint>

#define N_NODES 100000
#define N_EDGES 1600000
#define IN_F    512
#define HID_F   128
#define N_CLS   64

// ---------------- device scratch (no allocations allowed) ----------------
__device__ float g_h1[(size_t)N_NODES * HID_F];   // x@w1+b1
__device__ float g_h2[(size_t)N_NODES * HID_F];   // relu(spmm(h1))
__device__ float g_h3[(size_t)N_NODES * N_CLS];   // h2@w2+b2
__device__ int   g_deg[N_NODES + 1];
__device__ int   g_rowptr[N_NODES + 1];
__device__ int   g_fill[N_NODES];
__device__ int2  g_edge[N_EDGES];                 // {col, float_bits(val)}
// transposed, bf16-split weights (K-contiguous rows)
__device__ __align__(16) __nv_bfloat16 g_w1t_hi[HID_F * IN_F];   // [128][512]
__device__ __align__(16) __nv_bfloat16 g_w1t_lo[HID_F * IN_F];
__device__ __align__(16) __nv_bfloat16 g_w2t_hi[N_CLS * HID_F];  // [64][128]
__device__ __align__(16) __nv_bfloat16 g_w2t_lo[N_CLS * HID_F];

// ---------------- CSR build ----------------
__global__ void zero_deg_kernel() {
    int i = blockIdx.x * blockDim.x + threadIdx.x;
    if (i <= N_NODES) g_deg[i] = 0;
}
__global__ void count_kernel(const int* __restrict__ row) {
    int e = blockIdx.x * blockDim.x + threadIdx.x;
    if (e < N_EDGES) atomicAdd(&g_deg[row[e]], 1);
}
// single-block scan, shuffle-based
__global__ __launch_bounds__(1024) void scan_kernel() {
    __shared__ int wsum[32];
    int t = threadIdx.x;
    const int CH = (N_NODES + 1023) / 1024;  // 98
    int base = t * CH;
    int s = 0;
#pragma unroll 4
    for (int j = 0; j < CH; j++) {
        int i = base + j;
        if (i < N_NODES) s += g_deg[i];
    }
    int lane = t & 31, wid = t >> 5;
    int v = s;
#pragma unroll
    for (int d = 1; d < 32; d <<= 1) {
        int n = __shfl_up_sync(0xFFFFFFFF, v, d);
        if (lane >= d) v += n;
    }
    if (lane == 31) wsum[wid] = v;
    __syncthreads();
    if (wid == 0) {
        int w = wsum[lane];
#pragma unroll
        for (int d = 1; d < 32; d <<= 1) {
            int n = __shfl_up_sync(0xFFFFFFFF, w, d);
            if (lane >= d) w += n;
        }
        wsum[lane] = w;
    }
    __syncthreads();
    int run = v - s + (wid ? wsum[wid - 1] : 0);
    for (int j = 0; j < CH; j++) {
        int i = base + j;
        if (i < N_NODES) {
            int d = g_deg[i];
            g_rowptr[i] = run;
            g_fill[i]   = run;
            run += d;
        }
    }
    if (t == 1023) g_rowptr[N_NODES] = N_EDGES;
}
__global__ void scatter_kernel(const int* __restrict__ row, const int* __restrict__ col,
                               const float* __restrict__ val) {
    int e = blockIdx.x * blockDim.x + threadIdx.x;
    if (e < N_EDGES) {
        int r = row[e];
        int p = atomicAdd(&g_fill[r], 1);
        g_edge[p] = make_int2(col[e], __float_as_int(val[e]));
    }
}

// ---------------- weight prep: transpose + bf16 hi/lo split ----------------
__global__ void prep_w1t_kernel(const float* __restrict__ w1) {
    int idx = blockIdx.x * blockDim.x + threadIdx.x;
    if (idx < IN_F * HID_F) {
        int k = idx >> 7, n = idx & 127;
        float v = w1[idx];
        __nv_bfloat16 h = __float2bfloat16(v);
        float r = v - __bfloat162float(h);
        g_w1t_hi[n * IN_F + k] = h;
        g_w1t_lo[n * IN_F + k] = __float2bfloat16(r);
    }
}
__global__ void prep_w2t_kernel(const float* __restrict__ w2) {
    int idx = blockIdx.x * blockDim.x + threadIdx.x;
    if (idx < HID_F * N_CLS) {
        int k = idx >> 6, n = idx & 63;
        float v = w2[idx];
        __nv_bfloat16 h = __float2bfloat16(v);
        float r = v - __bfloat162float(h);
        g_w2t_hi[n * HID_F + k] = h;
        g_w2t_lo[n * HID_F + k] = __float2bfloat16(r);
    }
}

// ---------------- mma.sync bf16 GEMM (fp32-accurate via hi/lo split) --------
#define BK  64
#define LDK 72

__device__ __forceinline__ void mma_bf16(float* c, const uint32_t* a, const uint32_t* b) {
    asm volatile(
        "mma.sync.aligned.m16n8k16.row.col.f32.bf16.bf16.f32 "
        "{%0,%1,%2,%3}, {%4,%5,%6,%7}, {%8,%9}, {%0,%1,%2,%3};"
        : "+f"(c[0]), "+f"(c[1]), "+f"(c[2]), "+f"(c[3])
        : "r"(a[0]), "r"(a[1]), "r"(a[2]), "r"(a[3]), "r"(b[0]), "r"(b[1]));
}

__device__ __forceinline__ uint32_t pack_bf16x2(__nv_bfloat16 a, __nv_bfloat16 b) {
    __nv_bfloat162 p; p.x = a; p.y = b;
    return *reinterpret_cast<uint32_t*>(&p);
}

template <int BN, int K_TOTAL>
__global__ __launch_bounds__(256) void gemm_mma_kernel(
    const float* __restrict__ X,
    const __nv_bfloat16* __restrict__ Wt_hi,
    const __nv_bfloat16* __restrict__ Wt_lo,
    const float* __restrict__ Bias,
    float* __restrict__ O) {
    extern __shared__ char smraw[];
    __nv_bfloat16* As_hi = (__nv_bfloat16*)smraw;                 // [128][LDK]
    __nv_bfloat16* As_lo = As_hi + 128 * LDK;
    __nv_bfloat16* Bs_hi = As_lo + 128 * LDK;                     // [BN][LDK]
    __nv_bfloat16* Bs_lo = Bs_hi + BN * LDK;

    const int t = threadIdx.x;
    const int lane = t & 31;
    const int wid = t >> 5;
    const int warp_m = wid & 3;
    const int warp_n = wid >> 2;
    const int NT = BN / 16;
    const int n0 = warp_n * (BN / 2);
    const int row0 = blockIdx.x * 128;

    float acc[2][BN / 16][4];
#pragma unroll
    for (int mt = 0; mt < 2; mt++)
#pragma unroll
        for (int nt = 0; nt < NT; nt++)
#pragma unroll
            for (int i = 0; i < 4; i++) acc[mt][nt][i] = 0.f;

    const int gq = lane >> 2;
    const int gc2 = (lane & 3) * 2;

    for (int c = 0; c < K_TOTAL / BK; c++) {
        const int k0 = c * BK;
#pragma unroll
        for (int idx = t; idx < 128 * 16; idx += 256) {
            int row = idx >> 4;
            int col = (idx & 15) * 4;
            int gr = row0 + row;
            if (gr >= N_NODES) gr = N_NODES - 1;
            float4 v = *(const float4*)&X[(size_t)gr * K_TOTAL + k0 + col];
            __nv_bfloat16 h0 = __float2bfloat16(v.x);
            __nv_bfloat16 h1 = __float2bfloat16(v.y);
            __nv_bfloat16 h2 = __float2bfloat16(v.z);
            __nv_bfloat16 h3 = __float2bfloat16(v.w);
            uint2 hi, lo;
            hi.x = pack_bf16x2(h0, h1);
            hi.y = pack_bf16x2(h2, h3);
            lo.x = pack_bf16x2(__float2bfloat16(v.x - __bfloat162float(h0)),
                               __float2bfloat16(v.y - __bfloat162float(h1)));
            lo.y = pack_bf16x2(__float2bfloat16(v.z - __bfloat162float(h2)),
                               __float2bfloat16(v.w - __bfloat162float(h3)));
            *(uint2*)&As_hi[row * LDK + col] = hi;
            *(uint2*)&As_lo[row * LDK + col] = lo;
        }
#pragma unroll
        for (int idx = t; idx < BN * 8; idx += 256) {
            int row = idx >> 3;
            int q = (idx & 7) * 8;
            *(uint4*)&Bs_hi[row * LDK + q] = *(const uint4*)&Wt_hi[(size_t)row * K_TOTAL + k0 + q];
            *(uint4*)&Bs_lo[row * LDK + q] = *(const uint4*)&Wt_lo[(size_t)row * K_TOTAL + k0 + q];
        }
        __syncthreads();

#pragma unroll
        for (int ks = 0; ks < 4; ks++) {
            const int k = ks * 16;
            uint32_t ah[2][4], al[2][4];
#pragma unroll
            for (int mt = 0; mt < 2; mt++) {
                const int rb = warp_m * 32 + mt * 16 + gq;
                const __nv_bfloat16* ph = &As_hi[rb * LDK + k + gc2];
                const __nv_bfloat16* pl = &As_lo[rb * LDK + k + gc2];
                ah[mt][0] = *(const uint32_t*)(ph);
                ah[mt][1] = *(const uint32_t*)(ph + 8 * LDK);
                ah[mt][2] = *(const uint32_t*)(ph + 8);
                ah[mt][3] = *(const uint32_t*)(ph + 8 * LDK + 8);
                al[mt][0] = *(const uint32_t*)(pl);
                al[mt][1] = *(const uint32_t*)(pl + 8 * LDK);
                al[mt][2] = *(const uint32_t*)(pl + 8);
                al[mt][3] = *(const uint32_t*)(pl + 8 * LDK + 8);
            }
#pragma unroll
            for (int nt = 0; nt < NT; nt++) {
                const int nrow = n0 + nt * 8 + gq;
                const __nv_bfloat16* ph = &Bs_hi[nrow * LDK + k + gc2];
                const __nv_bfloat16* pl = &Bs_lo[nrow * LDK + k + gc2];
                uint32_t bh[2], bl[2];
                bh[0] = *(const uint32_t*)(ph);
                bh[1] = *(const uint32_t*)(ph + 8);
                bl[0] = *(const uint32_t*)(pl);
                bl[1] = *(const uint32_t*)(pl + 8);
#pragma unroll
                for (int mt = 0; mt < 2; mt++) {
                    mma_bf16(acc[mt][nt], ah[mt], bh);
                    mma_bf16(acc[mt][nt], ah[mt], bl);
                    mma_bf16(acc[mt][nt], al[mt], bh);
                }
            }
        }
        __syncthreads();
    }

#pragma unroll
    for (int nt = 0; nt < NT; nt++) {
        const int colb = n0 + nt * 8 + gc2;
        float2 bb = *(const float2*)&Bias[colb];
#pragma unroll
        for (int mt = 0; mt < 2; mt++) {
            int r0 = row0 + warp_m * 32 + mt * 16 + gq;
            if (r0 < N_NODES) {
                float2 o0;
                o0.x = acc[mt][nt][0] + bb.x;
                o0.y = acc[mt][nt][1] + bb.y;
                *(float2*)&O[(size_t)r0 * BN + colb] = o0;
            }
            int r1 = r0 + 8;
            if (r1 < N_NODES) {
                float2 o1;
                o1.x = acc[mt][nt][2] + bb.x;
                o1.y = acc[mt][nt][3] + bb.y;
                *(float2*)&O[(size_t)r1 * BN + colb] = o1;
            }
        }
    }
}

// ---------------- SpMM: warp-per-node, 4-edge unroll, no atomics ------------
__global__ __launch_bounds__(256) void spmm1_warp_kernel(
    const float* __restrict__ h1, float* __restrict__ h2) {
    int node = blockIdx.x * 8 + (threadIdx.x >> 5);
    int lane = threadIdx.x & 31;
    int s = g_rowptr[node], e = g_rowptr[node + 1];

    float4 a0 = make_float4(0.f, 0.f, 0.f, 0.f);
    float4 a1 = a0, a2 = a0, a3 = a0;
    const float4* H = (const float4*)h1;

    int j = s;
    for (; j + 3 < e; j += 4) {
        int2 e0 = g_edge[j],     e1 = g_edge[j + 1];
        int2 e2 = g_edge[j + 2], e3 = g_edge[j + 3];
        float v0 = __int_as_float(e0.y), v1 = __int_as_float(e1.y);
        float v2 = __int_as_float(e2.y), v3 = __int_as_float(e3.y);
        float4 x0 = H[(size_t)e0.x * 32 + lane];
        float4 x1 = H[(size_t)e1.x * 32 + lane];
        float4 x2 = H[(size_t)e2.x * 32 + lane];
        float4 x3 = H[(size_t)e3.x * 32 + lane];
        a0.x += v0 * x0.x; a0.y += v0 * x0.y; a0.z += v0 * x0.z; a0.w += v0 * x0.w;
        a1.x += v1 * x1.x; a1.y += v1 * x1.y; a1.z += v1 * x1.z; a1.w += v1 * x1.w;
        a2.x += v2 * x2.x; a2.y += v2 * x2.y; a2.z += v2 * x2.z; a2.w += v2 * x2.w;
        a3.x += v3 * x3.x; a3.y += v3 * x3.y; a3.z += v3 * x3.z; a3.w += v3 * x3.w;
    }
    for (; j < e; j++) {
        int2 ed = g_edge[j];
        float v = __int_as_float(ed.y);
        float4 x = H[(size_t)ed.x * 32 + lane];
        a0.x += v * x.x; a0.y += v * x.y; a0.z += v * x.z; a0.w += v * x.w;
    }
    float4 o;
    o.x = fmaxf(a0.x + a1.x + a2.x + a3.x, 0.f);
    o.y = fmaxf(a0.y + a1.y + a2.y + a3.y, 0.f);
    o.z = fmaxf(a0.z + a1.z + a2.z + a3.z, 0.f);
    o.w = fmaxf(a0.w + a1.w + a2.w + a3.w, 0.f);
    ((float4*)h2)[(size_t)node * 32 + lane] = o;
}

__global__ __launch_bounds__(256) void spmm2_warp_kernel(
    const float* __restrict__ h3, float* __restrict__ out) {
    int node = blockIdx.x * 8 + (threadIdx.x >> 5);
    int lane = threadIdx.x & 31;
    int s = g_rowptr[node], e = g_rowptr[node + 1];

    float2 a0 = make_float2(0.f, 0.f);
    float2 a1 = a0, a2 = a0, a3 = a0;
    const float2* H = (const float2*)h3;

    int j = s;
    for (; j + 3 < e; j += 4) {
        int2 e0 = g_edge[j],     e1 = g_edge[j + 1];
        int2 e2 = g_edge[j + 2], e3 = g_edge[j + 3];
        float v0 = __int_as_float(e0.y), v1 = __int_as_float(e1.y);
        float v2 = __int_as_float(e2.y), v3 = __int_as_float(e3.y);
        float2 x0 = H[(size_t)e0.x * 32 + lane];
        float2 x1 = H[(size_t)e1.x * 32 + lane];
        float2 x2 = H[(size_t)e2.x * 32 + lane];
        float2 x3 = H[(size_t)e3.x * 32 + lane];
        a0.x += v0 * x0.x; a0.y += v0 * x0.y;
        a1.x += v1 * x1.x; a1.y += v1 * x1.y;
        a2.x += v2 * x2.x; a2.y += v2 * x2.y;
        a3.x += v3 * x3.x; a3.y += v3 * x3.y;
    }
    for (; j < e; j++) {
        int2 ed = g_edge[j];
        float v = __int_as_float(ed.y);
        float2 x = H[(size_t)ed.x * 32 + lane];
        a0.x += v * x.x; a0.y += v * x.y;
    }
    float2 o;
    o.x = a0.x + a1.x + a2.x + a3.x;
    o.y = a0.y + a1.y + a2.y + a3.y;
    ((float2*)out)[(size_t)node * 32 + lane] = o;
}

// ---------------- launch ----------------
#define SMEM_G1 ((2 * 128 + 2 * HID_F) * LDK * 2)   // 73728
#define SMEM_G2 ((2 * 128 + 2 * N_CLS) * LDK * 2)   // 55296

extern "C" void kernel_launch(void* const* d_in, const int* in_sizes, int n_in,
                              void* d_out, int out_size) {
    const float* x       = (const float*)d_in[0];
    const int*   adj_row = (const int*)d_in[1];
    const int*   adj_col = (const int*)d_in[2];
    const float* adj_val = (const float*)d_in[3];
    const float* w1      = (const float*)d_in[4];
    const float* b1      = (const float*)d_in[5];
    const float* w2      = (const float*)d_in[6];
    const float* b2      = (const float*)d_in[7];
    float* out = (float*)d_out;

    float* h1 = nullptr; float* h2 = nullptr; float* h3 = nullptr;
    const __nv_bfloat16 *w1h, *w1l, *w2h, *w2l;
    cudaGetSymbolAddress((void**)&h1, g_h1);
    cudaGetSymbolAddress((void**)&h2, g_h2);
    cudaGetSymbolAddress((void**)&h3, g_h3);
    cudaGetSymbolAddress((void**)&w1h, g_w1t_hi);
    cudaGetSymbolAddress((void**)&w1l, g_w1t_lo);
    cudaGetSymbolAddress((void**)&w2h, g_w2t_hi);
    cudaGetSymbolAddress((void**)&w2l, g_w2t_lo);

    static cudaStream_t s_side = nullptr;
    static cudaEvent_t  ev_fork = nullptr, ev_join = nullptr;
    static bool init_done = false;
    if (!init_done) {
        cudaFuncSetAttribute(gemm_mma_kernel<HID_F, IN_F>,
                             cudaFuncAttributeMaxDynamicSharedMemorySize, SMEM_G1);
        cudaFuncSetAttribute(gemm_mma_kernel<N_CLS, HID_F>,
                             cudaFuncAttributeMaxDynamicSharedMemorySize, SMEM_G2);
        cudaStreamCreateWithFlags(&s_side, cudaStreamNonBlocking);
        cudaEventCreateWithFlags(&ev_fork, cudaEventDisableTiming);
        cudaEventCreateWithFlags(&ev_join, cudaEventDisableTiming);
        init_done = true;
    }

    // ---- fork: CSR build on side stream, concurrent with prep + gemm1 ----
    cudaEventRecord(ev_fork, 0);
    cudaStreamWaitEvent(s_side, ev_fork, 0);

    zero_deg_kernel<<<(N_NODES + 256) / 256, 256, 0, s_side>>>();
    count_kernel<<<(N_EDGES + 255) / 256, 256, 0, s_side>>>(adj_row);
    scan_kernel<<<1, 1024, 0, s_side>>>();
    scatter_kernel<<<(N_EDGES + 255) / 256, 256, 0, s_side>>>(adj_row, adj_col, adj_val);
    cudaEventRecord(ev_join, s_side);

    // ---- main stream: weight prep + gemm1 ----
    prep_w1t_kernel<<<(IN_F * HID_F + 255) / 256, 256>>>(w1);
    prep_w2t_kernel<<<(HID_F * N_CLS + 255) / 256, 256>>>(w2);
    gemm_mma_kernel<HID_F, IN_F>
        <<<(N_NODES + 127) / 128, 256, SMEM_G1>>>(x, w1h, w1l, b1, h1);

    // ---- join: spmm1 needs CSR + h1 ----
    cudaStreamWaitEvent(0, ev_join, 0);
    spmm1_warp_kernel<<<(N_NODES + 7) / 8, 256>>>(h1, h2);

    // Layer 2
    gemm_mma_kernel<N_CLS, HID_F>
        <<<(N_NODES + 127) / 128, 256, SMEM_G2>>>(h2, w2h, w2l, b2, h3);
    spmm2_warp_kernel<<<(N_NODES + 7) / 8, 256>>>(h3, out);
}

// round 6
// speedup vs baseline: 2.0073x; 1.1038x over previous
#include <cuda_runtime.h>
#include <cuda_bf16.h>
#include <cstdint>

#define N_NODES 100000
#define N_EDGES 1600000
#define IN_F    512
#define HID_F   128
#define N_CLS   64

// ---------------- device scratch (no allocations allowed) ----------------
__device__ __align__(16) float g_h1[(size_t)N_NODES * HID_F];
__device__ __align__(16) float g_h2[(size_t)N_NODES * HID_F];
__device__ __align__(16) float g_h3[(size_t)N_NODES * N_CLS];
__device__ int   g_deg[N_NODES + 1];
__device__ int   g_rowptr[N_NODES + 1];
__device__ int   g_fill[N_NODES];
__device__ int2  g_edge[N_EDGES];                 // {col, float_bits(val)}
__device__ __align__(16) __nv_bfloat16 g_w1t_hi[HID_F * IN_F];   // [128][512]
__device__ __align__(16) __nv_bfloat16 g_w1t_lo[HID_F * IN_F];
__device__ __align__(16) __nv_bfloat16 g_w2t_hi[N_CLS * HID_F];  // [64][128]
__device__ __align__(16) __nv_bfloat16 g_w2t_lo[N_CLS * HID_F];

// ---------------- small helpers ----------------
__device__ __forceinline__ uint32_t smem_u32(const void* p) {
    uint32_t a;
    asm("{ .reg .u64 t; cvta.to.shared.u64 t, %1; cvt.u32.u64 %0, t; }" : "=r"(a) : "l"(p));
    return a;
}
__device__ __forceinline__ void cp16(uint32_t dst, const void* src) {
    asm volatile("cp.async.ca.shared.global [%0], [%1], 16;" :: "r"(dst), "l"(src));
}
#define CP_COMMIT() asm volatile("cp.async.commit_group;" ::: "memory")
#define CP_WAIT(n)  asm volatile("cp.async.wait_group %0;" :: "n"(n) : "memory")

__device__ __forceinline__ void mma_bf16(float* c, const uint32_t* a, const uint32_t* b) {
    asm volatile(
        "mma.sync.aligned.m16n8k16.row.col.f32.bf16.bf16.f32 "
        "{%0,%1,%2,%3}, {%4,%5,%6,%7}, {%8,%9}, {%0,%1,%2,%3};"
        : "+f"(c[0]), "+f"(c[1]), "+f"(c[2]), "+f"(c[3])
        : "r"(a[0]), "r"(a[1]), "r"(a[2]), "r"(a[3]), "r"(b[0]), "r"(b[1]));
}
__device__ __forceinline__ uint32_t pack_bf16x2(__nv_bfloat16 a, __nv_bfloat16 b) {
    __nv_bfloat162 p; p.x = a; p.y = b;
    return *reinterpret_cast<uint32_t*>(&p);
}
// split float2 into hi bf16x2 (ret) and lo bf16x2 (out param)
__device__ __forceinline__ uint32_t split2(float2 v, uint32_t& lo) {
    __nv_bfloat16 h0 = __float2bfloat16(v.x), h1 = __float2bfloat16(v.y);
    lo = pack_bf16x2(__float2bfloat16(v.x - __bfloat162float(h0)),
                     __float2bfloat16(v.y - __bfloat162float(h1)));
    return pack_bf16x2(h0, h1);
}

// ---------------- CSR build ----------------
__global__ void zero_deg_kernel() {
    int i = blockIdx.x * blockDim.x + threadIdx.x;
    if (i <= N_NODES) g_deg[i] = 0;
}
__global__ void count_kernel(const int* __restrict__ row) {
    int e = blockIdx.x * blockDim.x + threadIdx.x;
    if (e < N_EDGES) atomicAdd(&g_deg[row[e]], 1);
}
__global__ __launch_bounds__(1024) void scan_kernel() {
    __shared__ int wsum[32];
    int t = threadIdx.x;
    const int CH = (N_NODES + 1023) / 1024;  // 98
    int base = t * CH;
    int s = 0;
#pragma unroll 4
    for (int j = 0; j < CH; j++) {
        int i = base + j;
        if (i < N_NODES) s += g_deg[i];
    }
    int lane = t & 31, wid = t >> 5;
    int v = s;
#pragma unroll
    for (int d = 1; d < 32; d <<= 1) {
        int n = __shfl_up_sync(0xFFFFFFFF, v, d);
        if (lane >= d) v += n;
    }
    if (lane == 31) wsum[wid] = v;
    __syncthreads();
    if (wid == 0) {
        int w = wsum[lane];
#pragma unroll
        for (int d = 1; d < 32; d <<= 1) {
            int n = __shfl_up_sync(0xFFFFFFFF, w, d);
            if (lane >= d) w += n;
        }
        wsum[lane] = w;
    }
    __syncthreads();
    int run = v - s + (wid ? wsum[wid - 1] : 0);
    for (int j = 0; j < CH; j++) {
        int i = base + j;
        if (i < N_NODES) {
            int d = g_deg[i];
            g_rowptr[i] = run;
            g_fill[i]   = run;
            run += d;
        }
    }
    if (t == 1023) g_rowptr[N_NODES] = N_EDGES;
}
__global__ void scatter_kernel(const int* __restrict__ row, const int* __restrict__ col,
                               const float* __restrict__ val) {
    int e = blockIdx.x * blockDim.x + threadIdx.x;
    if (e < N_EDGES) {
        int r = row[e];
        int p = atomicAdd(&g_fill[r], 1);
        g_edge[p] = make_int2(col[e], __float_as_int(val[e]));
    }
}

// ---------------- weight prep: transpose + bf16 hi/lo split ----------------
__global__ void prep_w1t_kernel(const float* __restrict__ w1) {
    int idx = blockIdx.x * blockDim.x + threadIdx.x;
    if (idx < IN_F * HID_F) {
        int k = idx >> 7, n = idx & 127;
        float v = w1[idx];
        __nv_bfloat16 h = __float2bfloat16(v);
        float r = v - __bfloat162float(h);
        g_w1t_hi[n * IN_F + k] = h;
        g_w1t_lo[n * IN_F + k] = __float2bfloat16(r);
    }
}
__global__ void prep_w2t_kernel(const float* __restrict__ w2) {
    int idx = blockIdx.x * blockDim.x + threadIdx.x;
    if (idx < HID_F * N_CLS) {
        int k = idx >> 6, n = idx & 63;
        float v = w2[idx];
        __nv_bfloat16 h = __float2bfloat16(v);
        float r = v - __bfloat162float(h);
        g_w2t_hi[n * HID_F + k] = h;
        g_w2t_lo[n * HID_F + k] = __float2bfloat16(r);
    }
}

// ---------------- cp.async double-buffered bf16-split GEMM ------------------
// C[128 x BN per CTA] = A[.,K] @ W[K,BN] + bias.
// A staged as fp32 (cp.async, 2-deep), split hi/lo at fragment build.
// B = pre-split bf16 weights (cp.async, 2-deep).
#define BK  64
#define LDK 72   // bf16 elements per B smem row
#define LDA 68   // fp32 elements per A stage row

template <int BN, int K_TOTAL>
__global__ __launch_bounds__(256) void gemm_pipe_kernel(
    const float* __restrict__ X,
    const __nv_bfloat16* __restrict__ Wt_hi,
    const __nv_bfloat16* __restrict__ Wt_lo,
    const float* __restrict__ Bias,
    float* __restrict__ O) {
    constexpr int NITER = K_TOTAL / BK;
    extern __shared__ char smraw[];
    float* Af = (float*)smraw;                                   // [2][128][LDA]
    __nv_bfloat16* Bh = (__nv_bfloat16*)(Af + 2 * 128 * LDA);    // [2][BN][LDK]
    __nv_bfloat16* Bl = Bh + 2 * BN * LDK;

    const int t = threadIdx.x;
    const int lane = t & 31;
    const int wid = t >> 5;
    const int warp_m = wid & 3;
    const int warp_n = wid >> 2;
    const int NT = BN / 16;
    const int n0 = warp_n * (BN / 2);
    const int row0 = blockIdx.x * 128;
    const int gq = lane >> 2;
    const int gc2 = (lane & 3) * 2;

    const uint32_t af_u = smem_u32(Af);
    const uint32_t bh_u = smem_u32(Bh);
    const uint32_t bl_u = smem_u32(Bl);

    auto issue = [&](int s) {
        const int buf = s & 1;
        const int k0 = s * BK;
#pragma unroll
        for (int i = 0; i < 8; i++) {               // A: 2048 float4 / 256 thr
            int idx = t + i * 256;
            int row = idx >> 4, c4 = (idx & 15) * 4;
            int gr = row0 + row;
            if (gr >= N_NODES) gr = N_NODES - 1;
            cp16(af_u + (uint32_t)(((buf * 128 + row) * LDA + c4) * 4),
                 X + (size_t)gr * K_TOTAL + k0 + c4);
        }
        constexpr int BCH = BN * 8 / 256;
#pragma unroll
        for (int i = 0; i < BCH; i++) {             // B: BN*8 uint4 per array
            int idx = t + i * 256;
            int row = idx >> 3, q = (idx & 7) * 8;
            cp16(bh_u + (uint32_t)(((buf * BN + row) * LDK + q) * 2),
                 Wt_hi + (size_t)row * K_TOTAL + k0 + q);
            cp16(bl_u + (uint32_t)(((buf * BN + row) * LDK + q) * 2),
                 Wt_lo + (size_t)row * K_TOTAL + k0 + q);
        }
        CP_COMMIT();
    };

    float acc[2][BN / 16][4];
#pragma unroll
    for (int mt = 0; mt < 2; mt++)
#pragma unroll
        for (int nt = 0; nt < NT; nt++)
#pragma unroll
            for (int i = 0; i < 4; i++) acc[mt][nt][i] = 0.f;

    issue(0);
    if (NITER > 1) issue(1);

    for (int c = 0; c < NITER; c++) {
        if (c >= NITER - 1) { CP_WAIT(0); } else { CP_WAIT(1); }
        __syncthreads();
        const int buf = c & 1;

#pragma unroll
        for (int ks = 0; ks < 4; ks++) {
            const int k = ks * 16;
            uint32_t ah[2][4], al[2][4];
#pragma unroll
            for (int mt = 0; mt < 2; mt++) {
                const int rb = buf * 128 + warp_m * 32 + mt * 16 + gq;
                const float* p0 = &Af[rb * LDA + k + gc2];
                float2 v0 = *(const float2*)(p0);
                float2 v1 = *(const float2*)(p0 + 8 * LDA);
                float2 v2 = *(const float2*)(p0 + 8);
                float2 v3 = *(const float2*)(p0 + 8 * LDA + 8);
                ah[mt][0] = split2(v0, al[mt][0]);
                ah[mt][1] = split2(v1, al[mt][1]);
                ah[mt][2] = split2(v2, al[mt][2]);
                ah[mt][3] = split2(v3, al[mt][3]);
            }
#pragma unroll
            for (int nt = 0; nt < NT; nt++) {
                const int nrow = buf * BN + n0 + nt * 8 + gq;
                const __nv_bfloat16* ph = &Bh[nrow * LDK + k + gc2];
                const __nv_bfloat16* pl = &Bl[nrow * LDK + k + gc2];
                uint32_t bh[2], bl[2];
                bh[0] = *(const uint32_t*)(ph);
                bh[1] = *(const uint32_t*)(ph + 8);
                bl[0] = *(const uint32_t*)(pl);
                bl[1] = *(const uint32_t*)(pl + 8);
#pragma unroll
                for (int mt = 0; mt < 2; mt++) {
                    mma_bf16(acc[mt][nt], ah[mt], bh);
                    mma_bf16(acc[mt][nt], ah[mt], bl);
                    mma_bf16(acc[mt][nt], al[mt], bh);
                }
            }
        }
        __syncthreads();
        if (c + 2 < NITER) issue(c + 2);
    }

#pragma unroll
    for (int nt = 0; nt < NT; nt++) {
        const int colb = n0 + nt * 8 + gc2;
        float2 bb = *(const float2*)&Bias[colb];
#pragma unroll
        for (int mt = 0; mt < 2; mt++) {
            int r0 = row0 + warp_m * 32 + mt * 16 + gq;
            if (r0 < N_NODES) {
                float2 o0;
                o0.x = acc[mt][nt][0] + bb.x;
                o0.y = acc[mt][nt][1] + bb.y;
                *(float2*)&O[(size_t)r0 * BN + colb] = o0;
            }
            int r1 = r0 + 8;
            if (r1 < N_NODES) {
                float2 o1;
                o1.x = acc[mt][nt][2] + bb.x;
                o1.y = acc[mt][nt][3] + bb.y;
                *(float2*)&O[(size_t)r1 * BN + colb] = o1;
            }
        }
    }
}

// ---------------- SpMM: warp-per-node, 4-edge unroll, no atomics ------------
__global__ __launch_bounds__(256) void spmm1_warp_kernel(
    const float* __restrict__ h1, float* __restrict__ h2) {
    int node = blockIdx.x * 8 + (threadIdx.x >> 5);
    int lane = threadIdx.x & 31;
    int s = g_rowptr[node], e = g_rowptr[node + 1];

    float4 a0 = make_float4(0.f, 0.f, 0.f, 0.f);
    float4 a1 = a0, a2 = a0, a3 = a0;
    const float4* H = (const float4*)h1;

    int j = s;
    for (; j + 3 < e; j += 4) {
        int2 e0 = g_edge[j],     e1 = g_edge[j + 1];
        int2 e2 = g_edge[j + 2], e3 = g_edge[j + 3];
        float v0 = __int_as_float(e0.y), v1 = __int_as_float(e1.y);
        float v2 = __int_as_float(e2.y), v3 = __int_as_float(e3.y);
        float4 x0 = H[(size_t)e0.x * 32 + lane];
        float4 x1 = H[(size_t)e1.x * 32 + lane];
        float4 x2 = H[(size_t)e2.x * 32 + lane];
        float4 x3 = H[(size_t)e3.x * 32 + lane];
        a0.x += v0 * x0.x; a0.y += v0 * x0.y; a0.z += v0 * x0.z; a0.w += v0 * x0.w;
        a1.x += v1 * x1.x; a1.y += v1 * x1.y; a1.z += v1 * x1.z; a1.w += v1 * x1.w;
        a2.x += v2 * x2.x; a2.y += v2 * x2.y; a2.z += v2 * x2.z; a2.w += v2 * x2.w;
        a3.x += v3 * x3.x; a3.y += v3 * x3.y; a3.z += v3 * x3.z; a3.w += v3 * x3.w;
    }
    for (; j < e; j++) {
        int2 ed = g_edge[j];
        float v = __int_as_float(ed.y);
        float4 x = H[(size_t)ed.x * 32 + lane];
        a0.x += v * x.x; a0.y += v * x.y; a0.z += v * x.z; a0.w += v * x.w;
    }
    float4 o;
    o.x = fmaxf(a0.x + a1.x + a2.x + a3.x, 0.f);
    o.y = fmaxf(a0.y + a1.y + a2.y + a3.y, 0.f);
    o.z = fmaxf(a0.z + a1.z + a2.z + a3.z, 0.f);
    o.w = fmaxf(a0.w + a1.w + a2.w + a3.w, 0.f);
    ((float4*)h2)[(size_t)node * 32 + lane] = o;
}

__global__ __launch_bounds__(256) void spmm2_warp_kernel(
    const float* __restrict__ h3, float* __restrict__ out) {
    int node = blockIdx.x * 8 + (threadIdx.x >> 5);
    int lane = threadIdx.x & 31;
    int s = g_rowptr[node], e = g_rowptr[node + 1];

    float2 a0 = make_float2(0.f, 0.f);
    float2 a1 = a0, a2 = a0, a3 = a0;
    const float2* H = (const float2*)h3;

    int j = s;
    for (; j + 3 < e; j += 4) {
        int2 e0 = g_edge[j],     e1 = g_edge[j + 1];
        int2 e2 = g_edge[j + 2], e3 = g_edge[j + 3];
        float v0 = __int_as_float(e0.y), v1 = __int_as_float(e1.y);
        float v2 = __int_as_float(e2.y), v3 = __int_as_float(e3.y);
        float2 x0 = H[(size_t)e0.x * 32 + lane];
        float2 x1 = H[(size_t)e1.x * 32 + lane];
        float2 x2 = H[(size_t)e2.x * 32 + lane];
        float2 x3 = H[(size_t)e3.x * 32 + lane];
        a0.x += v0 * x0.x; a0.y += v0 * x0.y;
        a1.x += v1 * x1.x; a1.y += v1 * x1.y;
        a2.x += v2 * x2.x; a2.y += v2 * x2.y;
        a3.x += v3 * x3.x; a3.y += v3 * x3.y;
    }
    for (; j < e; j++) {
        int2 ed = g_edge[j];
        float v = __int_as_float(ed.y);
        float2 x = H[(size_t)ed.x * 32 + lane];
        a0.x += v * x.x; a0.y += v * x.y;
    }
    float2 o;
    o.x = a0.x + a1.x + a2.x + a3.x;
    o.y = a0.y + a1.y + a2.y + a3.y;
    ((float2*)out)[(size_t)node * 32 + lane] = o;
}

// ---------------- launch ----------------
#define SMEM_PIPE(BN) (2 * 128 * LDA * 4 + 2 * 2 * (BN) * LDK * 2)
// BN=128: 69632 + 73728 = 143360 ; BN=64: 69632 + 36864 = 106496

extern "C" void kernel_launch(void* const* d_in, const int* in_sizes, int n_in,
                              void* d_out, int out_size) {
    const float* x       = (const float*)d_in[0];
    const int*   adj_row = (const int*)d_in[1];
    const int*   adj_col = (const int*)d_in[2];
    const float* adj_val = (const float*)d_in[3];
    const float* w1      = (const float*)d_in[4];
    const float* b1      = (const float*)d_in[5];
    const float* w2      = (const float*)d_in[6];
    const float* b2      = (const float*)d_in[7];
    float* out = (float*)d_out;

    float* h1 = nullptr; float* h2 = nullptr; float* h3 = nullptr;
    const __nv_bfloat16 *w1h, *w1l, *w2h, *w2l;
    cudaGetSymbolAddress((void**)&h1, g_h1);
    cudaGetSymbolAddress((void**)&h2, g_h2);
    cudaGetSymbolAddress((void**)&h3, g_h3);
    cudaGetSymbolAddress((void**)&w1h, g_w1t_hi);
    cudaGetSymbolAddress((void**)&w1l, g_w1t_lo);
    cudaGetSymbolAddress((void**)&w2h, g_w2t_hi);
    cudaGetSymbolAddress((void**)&w2l, g_w2t_lo);

    static cudaStream_t s_side = nullptr;
    static cudaEvent_t  ev_fork = nullptr, ev_join = nullptr;
    static bool init_done = false;
    if (!init_done) {
        cudaFuncSetAttribute(gemm_pipe_kernel<HID_F, IN_F>,
                             cudaFuncAttributeMaxDynamicSharedMemorySize, SMEM_PIPE(HID_F));
        cudaFuncSetAttribute(gemm_pipe_kernel<N_CLS, HID_F>,
                             cudaFuncAttributeMaxDynamicSharedMemorySize, SMEM_PIPE(N_CLS));
        cudaStreamCreateWithFlags(&s_side, cudaStreamNonBlocking);
        cudaEventCreateWithFlags(&ev_fork, cudaEventDisableTiming);
        cudaEventCreateWithFlags(&ev_join, cudaEventDisableTiming);
        init_done = true;
    }

    // ---- fork: CSR build on side stream, concurrent with prep + gemm1 ----
    cudaEventRecord(ev_fork, 0);
    cudaStreamWaitEvent(s_side, ev_fork, 0);

    zero_deg_kernel<<<(N_NODES + 256) / 256, 256, 0, s_side>>>();
    count_kernel<<<(N_EDGES + 255) / 256, 256, 0, s_side>>>(adj_row);
    scan_kernel<<<1, 1024, 0, s_side>>>();
    scatter_kernel<<<(N_EDGES + 255) / 256, 256, 0, s_side>>>(adj_row, adj_col, adj_val);
    cudaEventRecord(ev_join, s_side);

    // ---- main stream: weight prep + gemm1 ----
    prep_w1t_kernel<<<(IN_F * HID_F + 255) / 256, 256>>>(w1);
    prep_w2t_kernel<<<(HID_F * N_CLS + 255) / 256, 256>>>(w2);
    gemm_pipe_kernel<HID_F, IN_F>
        <<<(N_NODES + 127) / 128, 256, SMEM_PIPE(HID_F)>>>(x, w1h, w1l, b1, h1);

    // ---- join: spmm1 needs CSR + h1 ----
    cudaStreamWaitEvent(0, ev_join, 0);
    spmm1_warp_kernel<<<(N_NODES + 7) / 8, 256>>>(h1, h2);

    // Layer 2
    gemm_pipe_kernel<N_CLS, HID_F>
        <<<(N_NODES + 127) / 128, 256, SMEM_PIPE(N_CLS)>>>(h2, w2h, w2l, b2, h3);
    spmm2_warp_kernel<<<(N_NODES + 7) / 8, 256>>>(h3, out);
}

// round 7
// speedup vs baseline: 2.0742x; 1.0333x over previous
#include <cuda_runtime.h>
#include <cuda_bf16.h>
#include <cstdint>

#define N_NODES 100000
#define N_EDGES 1600000
#define IN_F    512
#define HID_F   128
#define N_CLS   64
#define HALF_N  50048            // split point, multiple of 128 and 8

// ---------------- device scratch (no allocations allowed) ----------------
__device__ __align__(16) float g_h1[(size_t)N_NODES * HID_F];
__device__ __align__(16) float g_h2[(size_t)N_NODES * HID_F];
__device__ __align__(16) float g_h3[(size_t)N_NODES * N_CLS];
__device__ int   g_deg[N_NODES + 1];
__device__ int   g_rowptr[N_NODES + 1];
__device__ int   g_fill[N_NODES];
__device__ int2  g_edge[N_EDGES];                 // {col, float_bits(val)}
__device__ __align__(16) __nv_bfloat16 g_w1t_hi[HID_F * IN_F];   // [128][512]
__device__ __align__(16) __nv_bfloat16 g_w1t_lo[HID_F * IN_F];
__device__ __align__(16) __nv_bfloat16 g_w2t_hi[N_CLS * HID_F];  // [64][128]
__device__ __align__(16) __nv_bfloat16 g_w2t_lo[N_CLS * HID_F];

// ---------------- small helpers ----------------
__device__ __forceinline__ uint32_t smem_u32(const void* p) {
    uint32_t a;
    asm("{ .reg .u64 t; cvta.to.shared.u64 t, %1; cvt.u32.u64 %0, t; }" : "=r"(a) : "l"(p));
    return a;
}
__device__ __forceinline__ void cp16(uint32_t dst, const void* src) {
    asm volatile("cp.async.ca.shared.global [%0], [%1], 16;" :: "r"(dst), "l"(src));
}
#define CP_COMMIT() asm volatile("cp.async.commit_group;" ::: "memory")
#define CP_WAIT(n)  asm volatile("cp.async.wait_group %0;" :: "n"(n) : "memory")

__device__ __forceinline__ void mma_bf16(float* c, const uint32_t* a, const uint32_t* b) {
    asm volatile(
        "mma.sync.aligned.m16n8k16.row.col.f32.bf16.bf16.f32 "
        "{%0,%1,%2,%3}, {%4,%5,%6,%7}, {%8,%9}, {%0,%1,%2,%3};"
        : "+f"(c[0]), "+f"(c[1]), "+f"(c[2]), "+f"(c[3])
        : "r"(a[0]), "r"(a[1]), "r"(a[2]), "r"(a[3]), "r"(b[0]), "r"(b[1]));
}
__device__ __forceinline__ uint32_t pack_bf16x2(__nv_bfloat16 a, __nv_bfloat16 b) {
    __nv_bfloat162 p; p.x = a; p.y = b;
    return *reinterpret_cast<uint32_t*>(&p);
}
__device__ __forceinline__ uint32_t split2(float2 v, uint32_t& lo) {
    __nv_bfloat16 h0 = __float2bfloat16(v.x), h1 = __float2bfloat16(v.y);
    lo = pack_bf16x2(__float2bfloat16(v.x - __bfloat162float(h0)),
                     __float2bfloat16(v.y - __bfloat162float(h1)));
    return pack_bf16x2(h0, h1);
}

// ---------------- CSR build ----------------
__global__ void zero_deg_kernel() {
    int i = blockIdx.x * blockDim.x + threadIdx.x;
    if (i <= N_NODES) g_deg[i] = 0;
}
__global__ void count_kernel(const int* __restrict__ row) {
    int e = blockIdx.x * blockDim.x + threadIdx.x;
    if (e < N_EDGES) atomicAdd(&g_deg[row[e]], 1);
}
__global__ __launch_bounds__(1024) void scan_kernel() {
    __shared__ int wsum[32];
    int t = threadIdx.x;
    const int CH = (N_NODES + 1023) / 1024;  // 98
    int base = t * CH;
    int s = 0;
#pragma unroll 4
    for (int j = 0; j < CH; j++) {
        int i = base + j;
        if (i < N_NODES) s += g_deg[i];
    }
    int lane = t & 31, wid = t >> 5;
    int v = s;
#pragma unroll
    for (int d = 1; d < 32; d <<= 1) {
        int n = __shfl_up_sync(0xFFFFFFFF, v, d);
        if (lane >= d) v += n;
    }
    if (lane == 31) wsum[wid] = v;
    __syncthreads();
    if (wid == 0) {
        int w = wsum[lane];
#pragma unroll
        for (int d = 1; d < 32; d <<= 1) {
            int n = __shfl_up_sync(0xFFFFFFFF, w, d);
            if (lane >= d) w += n;
        }
        wsum[lane] = w;
    }
    __syncthreads();
    int run = v - s + (wid ? wsum[wid - 1] : 0);
    for (int j = 0; j < CH; j++) {
        int i = base + j;
        if (i < N_NODES) {
            int d = g_deg[i];
            g_rowptr[i] = run;
            g_fill[i]   = run;
            run += d;
        }
    }
    if (t == 1023) g_rowptr[N_NODES] = N_EDGES;
}
__global__ void scatter_kernel(const int* __restrict__ row, const int* __restrict__ col,
                               const float* __restrict__ val) {
    int e = blockIdx.x * blockDim.x + threadIdx.x;
    if (e < N_EDGES) {
        int r = row[e];
        int p = atomicAdd(&g_fill[r], 1);
        g_edge[p] = make_int2(col[e], __float_as_int(val[e]));
    }
}

// ---------------- weight prep: transpose + bf16 hi/lo split ----------------
__global__ void prep_w1t_kernel(const float* __restrict__ w1) {
    int idx = blockIdx.x * blockDim.x + threadIdx.x;
    if (idx < IN_F * HID_F) {
        int k = idx >> 7, n = idx & 127;
        float v = w1[idx];
        __nv_bfloat16 h = __float2bfloat16(v);
        float r = v - __bfloat162float(h);
        g_w1t_hi[n * IN_F + k] = h;
        g_w1t_lo[n * IN_F + k] = __float2bfloat16(r);
    }
}
__global__ void prep_w2t_kernel(const float* __restrict__ w2) {
    int idx = blockIdx.x * blockDim.x + threadIdx.x;
    if (idx < HID_F * N_CLS) {
        int k = idx >> 6, n = idx & 63;
        float v = w2[idx];
        __nv_bfloat16 h = __float2bfloat16(v);
        float r = v - __bfloat162float(h);
        g_w2t_hi[n * HID_F + k] = h;
        g_w2t_lo[n * HID_F + k] = __float2bfloat16(r);
    }
}

// ---------------- cp.async pipelined bf16-split GEMM ------------------------
// A: fp32, 2-deep cp.async ring. B: pre-split bf16 weights, SINGLE buffer
// (L2-resident; reloaded per chunk right after the consuming barrier).
#define BK  64
#define LDK 72   // bf16 elements per B smem row
#define LDA 68   // fp32 elements per A stage row

template <int BN, int K_TOTAL>
__global__ __launch_bounds__(256) void gemm_pipe_kernel(
    const float* __restrict__ X,
    const __nv_bfloat16* __restrict__ Wt_hi,
    const __nv_bfloat16* __restrict__ Wt_lo,
    const float* __restrict__ Bias,
    float* __restrict__ O,
    int row_base, int row_limit) {
    constexpr int NITER = K_TOTAL / BK;
    extern __shared__ char smraw[];
    float* Af = (float*)smraw;                                   // [2][128][LDA]
    __nv_bfloat16* Bh = (__nv_bfloat16*)(Af + 2 * 128 * LDA);    // [BN][LDK]
    __nv_bfloat16* Bl = Bh + BN * LDK;

    const int t = threadIdx.x;
    const int lane = t & 31;
    const int wid = t >> 5;
    const int warp_m = wid & 3;
    const int warp_n = wid >> 2;
    const int NT = BN / 16;
    const int n0 = warp_n * (BN / 2);
    const int row0 = row_base + blockIdx.x * 128;
    const int gq = lane >> 2;
    const int gc2 = (lane & 3) * 2;

    const uint32_t af_u = smem_u32(Af);
    const uint32_t bh_u = smem_u32(Bh);
    const uint32_t bl_u = smem_u32(Bl);

    auto issueA = [&](int s) {
        const int buf = s & 1;
        const int k0 = s * BK;
#pragma unroll
        for (int i = 0; i < 8; i++) {               // 2048 float4 / 256 thr
            int idx = t + i * 256;
            int row = idx >> 4, c4 = (idx & 15) * 4;
            int gr = row0 + row;
            if (gr >= N_NODES) gr = N_NODES - 1;
            cp16(af_u + (uint32_t)(((buf * 128 + row) * LDA + c4) * 4),
                 X + (size_t)gr * K_TOTAL + k0 + c4);
        }
    };
    auto issueB = [&](int s) {
        const int k0 = s * BK;
        constexpr int BCH = BN * 8 / 256;
#pragma unroll
        for (int i = 0; i < BCH; i++) {
            int idx = t + i * 256;
            int row = idx >> 3, q = (idx & 7) * 8;
            cp16(bh_u + (uint32_t)((row * LDK + q) * 2),
                 Wt_hi + (size_t)row * K_TOTAL + k0 + q);
            cp16(bl_u + (uint32_t)((row * LDK + q) * 2),
                 Wt_lo + (size_t)row * K_TOTAL + k0 + q);
        }
    };

    float acc[2][BN / 16][4];
#pragma unroll
    for (int mt = 0; mt < 2; mt++)
#pragma unroll
        for (int nt = 0; nt < NT; nt++)
#pragma unroll
            for (int i = 0; i < 4; i++) acc[mt][nt][i] = 0.f;

    // prologue: B0, A0, A1 as separate groups; wait all but newest
    issueB(0); CP_COMMIT();
    issueA(0); CP_COMMIT();
    if (NITER > 1) { issueA(1); CP_COMMIT(); CP_WAIT(1); }
    else           { CP_WAIT(0); }
    __syncthreads();

    for (int c = 0; c < NITER; c++) {
        const int buf = c & 1;
#pragma unroll
        for (int ks = 0; ks < 4; ks++) {
            const int k = ks * 16;
            uint32_t ah[2][4], al[2][4];
#pragma unroll
            for (int mt = 0; mt < 2; mt++) {
                const int rb = buf * 128 + warp_m * 32 + mt * 16 + gq;
                const float* p0 = &Af[rb * LDA + k + gc2];
                float2 v0 = *(const float2*)(p0);
                float2 v1 = *(const float2*)(p0 + 8 * LDA);
                float2 v2 = *(const float2*)(p0 + 8);
                float2 v3 = *(const float2*)(p0 + 8 * LDA + 8);
                ah[mt][0] = split2(v0, al[mt][0]);
                ah[mt][1] = split2(v1, al[mt][1]);
                ah[mt][2] = split2(v2, al[mt][2]);
                ah[mt][3] = split2(v3, al[mt][3]);
            }
#pragma unroll
            for (int nt = 0; nt < NT; nt++) {
                const int nrow = n0 + nt * 8 + gq;
                const __nv_bfloat16* ph = &Bh[nrow * LDK + k + gc2];
                const __nv_bfloat16* pl = &Bl[nrow * LDK + k + gc2];
                uint32_t bh[2], bl[2];
                bh[0] = *(const uint32_t*)(ph);
                bh[1] = *(const uint32_t*)(ph + 8);
                bl[0] = *(const uint32_t*)(pl);
                bl[1] = *(const uint32_t*)(pl + 8);
#pragma unroll
                for (int mt = 0; mt < 2; mt++) {
                    mma_bf16(acc[mt][nt], ah[mt], bh);
                    mma_bf16(acc[mt][nt], ah[mt], bl);
                    mma_bf16(acc[mt][nt], al[mt], bh);
                }
            }
        }
        __syncthreads();            // everyone done with A(c) buf and B(c)
        if (c + 1 < NITER) {
            issueB(c + 1); CP_COMMIT();
            if (c + 2 < NITER) { issueA(c + 2); CP_COMMIT(); CP_WAIT(1); }
            else               { CP_WAIT(0); }
            __syncthreads();
        }
    }

#pragma unroll
    for (int nt = 0; nt < NT; nt++) {
        const int colb = n0 + nt * 8 + gc2;
        float2 bb = *(const float2*)&Bias[colb];
#pragma unroll
        for (int mt = 0; mt < 2; mt++) {
            int r0 = row0 + warp_m * 32 + mt * 16 + gq;
            if (r0 < row_limit) {
                float2 o0;
                o0.x = acc[mt][nt][0] + bb.x;
                o0.y = acc[mt][nt][1] + bb.y;
                *(float2*)&O[(size_t)r0 * BN + colb] = o0;
            }
            int r1 = r0 + 8;
            if (r1 < row_limit) {
                float2 o1;
                o1.x = acc[mt][nt][2] + bb.x;
                o1.y = acc[mt][nt][3] + bb.y;
                *(float2*)&O[(size_t)r1 * BN + colb] = o1;
            }
        }
    }
}

// ---------------- SpMM: warp-per-node, 4-edge unroll, no atomics ------------
__global__ __launch_bounds__(256) void spmm1_warp_kernel(
    const float* __restrict__ h1, float* __restrict__ h2, int node_base) {
    int node = node_base + blockIdx.x * 8 + (threadIdx.x >> 5);
    int lane = threadIdx.x & 31;
    int s = g_rowptr[node], e = g_rowptr[node + 1];

    float4 a0 = make_float4(0.f, 0.f, 0.f, 0.f);
    float4 a1 = a0, a2 = a0, a3 = a0;
    const float4* H = (const float4*)h1;

    int j = s;
    for (; j + 3 < e; j += 4) {
        int2 e0 = g_edge[j],     e1 = g_edge[j + 1];
        int2 e2 = g_edge[j + 2], e3 = g_edge[j + 3];
        float v0 = __int_as_float(e0.y), v1 = __int_as_float(e1.y);
        float v2 = __int_as_float(e2.y), v3 = __int_as_float(e3.y);
        float4 x0 = H[(size_t)e0.x * 32 + lane];
        float4 x1 = H[(size_t)e1.x * 32 + lane];
        float4 x2 = H[(size_t)e2.x * 32 + lane];
        float4 x3 = H[(size_t)e3.x * 32 + lane];
        a0.x += v0 * x0.x; a0.y += v0 * x0.y; a0.z += v0 * x0.z; a0.w += v0 * x0.w;
        a1.x += v1 * x1.x; a1.y += v1 * x1.y; a1.z += v1 * x1.z; a1.w += v1 * x1.w;
        a2.x += v2 * x2.x; a2.y += v2 * x2.y; a2.z += v2 * x2.z; a2.w += v2 * x2.w;
        a3.x += v3 * x3.x; a3.y += v3 * x3.y; a3.z += v3 * x3.z; a3.w += v3 * x3.w;
    }
    for (; j < e; j++) {
        int2 ed = g_edge[j];
        float v = __int_as_float(ed.y);
        float4 x = H[(size_t)ed.x * 32 + lane];
        a0.x += v * x.x; a0.y += v * x.y; a0.z += v * x.z; a0.w += v * x.w;
    }
    float4 o;
    o.x = fmaxf(a0.x + a1.x + a2.x + a3.x, 0.f);
    o.y = fmaxf(a0.y + a1.y + a2.y + a3.y, 0.f);
    o.z = fmaxf(a0.z + a1.z + a2.z + a3.z, 0.f);
    o.w = fmaxf(a0.w + a1.w + a2.w + a3.w, 0.f);
    ((float4*)h2)[(size_t)node * 32 + lane] = o;
}

__global__ __launch_bounds__(256) void spmm2_warp_kernel(
    const float* __restrict__ h3, float* __restrict__ out) {
    int node = blockIdx.x * 8 + (threadIdx.x >> 5);
    int lane = threadIdx.x & 31;
    int s = g_rowptr[node], e = g_rowptr[node + 1];

    float2 a0 = make_float2(0.f, 0.f);
    float2 a1 = a0, a2 = a0, a3 = a0;
    const float2* H = (const float2*)h3;

    int j = s;
    for (; j + 3 < e; j += 4) {
        int2 e0 = g_edge[j],     e1 = g_edge[j + 1];
        int2 e2 = g_edge[j + 2], e3 = g_edge[j + 3];
        float v0 = __int_as_float(e0.y), v1 = __int_as_float(e1.y);
        float v2 = __int_as_float(e2.y), v3 = __int_as_float(e3.y);
        float2 x0 = H[(size_t)e0.x * 32 + lane];
        float2 x1 = H[(size_t)e1.x * 32 + lane];
        float2 x2 = H[(size_t)e2.x * 32 + lane];
        float2 x3 = H[(size_t)e3.x * 32 + lane];
        a0.x += v0 * x0.x; a0.y += v0 * x0.y;
        a1.x += v1 * x1.x; a1.y += v1 * x1.y;
        a2.x += v2 * x2.x; a2.y += v2 * x2.y;
        a3.x += v3 * x3.x; a3.y += v3 * x3.y;
    }
    for (; j < e; j++) {
        int2 ed = g_edge[j];
        float v = __int_as_float(ed.y);
        float2 x = H[(size_t)ed.x * 32 + lane];
        a0.x += v * x.x; a0.y += v * x.y;
    }
    float2 o;
    o.x = a0.x + a1.x + a2.x + a3.x;
    o.y = a0.y + a1.y + a2.y + a3.y;
    ((float2*)out)[(size_t)node * 32 + lane] = o;
}

// ---------------- launch ----------------
#define SMEM_PIPE(BN) (2 * 128 * LDA * 4 + 2 * (BN) * LDK * 2)
// BN=128: 69632 + 36864 = 106496 ; BN=64: 69632 + 18432 = 88064

extern "C" void kernel_launch(void* const* d_in, const int* in_sizes, int n_in,
                              void* d_out, int out_size) {
    const float* x       = (const float*)d_in[0];
    const int*   adj_row = (const int*)d_in[1];
    const int*   adj_col = (const int*)d_in[2];
    const float* adj_val = (const float*)d_in[3];
    const float* w1      = (const float*)d_in[4];
    const float* b1      = (const float*)d_in[5];
    const float* w2      = (const float*)d_in[6];
    const float* b2      = (const float*)d_in[7];
    float* out = (float*)d_out;

    float* h1 = nullptr; float* h2 = nullptr; float* h3 = nullptr;
    const __nv_bfloat16 *w1h, *w1l, *w2h, *w2l;
    cudaGetSymbolAddress((void**)&h1, g_h1);
    cudaGetSymbolAddress((void**)&h2, g_h2);
    cudaGetSymbolAddress((void**)&h3, g_h3);
    cudaGetSymbolAddress((void**)&w1h, g_w1t_hi);
    cudaGetSymbolAddress((void**)&w1l, g_w1t_lo);
    cudaGetSymbolAddress((void**)&w2h, g_w2t_hi);
    cudaGetSymbolAddress((void**)&w2l, g_w2t_lo);

    static cudaStream_t s_side = nullptr;
    static cudaEvent_t ev_fork = nullptr, ev_join = nullptr, ev_g1 = nullptr, ev_l2 = nullptr;
    static bool init_done = false;
    if (!init_done) {
        cudaFuncSetAttribute(gemm_pipe_kernel<HID_F, IN_F>,
                             cudaFuncAttributeMaxDynamicSharedMemorySize, SMEM_PIPE(HID_F));
        cudaFuncSetAttribute(gemm_pipe_kernel<N_CLS, HID_F>,
                             cudaFuncAttributeMaxDynamicSharedMemorySize, SMEM_PIPE(N_CLS));
        cudaStreamCreateWithFlags(&s_side, cudaStreamNonBlocking);
        cudaEventCreateWithFlags(&ev_fork, cudaEventDisableTiming);
        cudaEventCreateWithFlags(&ev_join, cudaEventDisableTiming);
        cudaEventCreateWithFlags(&ev_g1,   cudaEventDisableTiming);
        cudaEventCreateWithFlags(&ev_l2,   cudaEventDisableTiming);
        init_done = true;
    }

    // ---- fork: CSR build on side stream, concurrent with prep + gemm1 ----
    cudaEventRecord(ev_fork, 0);
    cudaStreamWaitEvent(s_side, ev_fork, 0);

    zero_deg_kernel<<<(N_NODES + 256) / 256, 256, 0, s_side>>>();
    count_kernel<<<(N_EDGES + 255) / 256, 256, 0, s_side>>>(adj_row);
    scan_kernel<<<1, 1024, 0, s_side>>>();
    scatter_kernel<<<(N_EDGES + 255) / 256, 256, 0, s_side>>>(adj_row, adj_col, adj_val);
    cudaEventRecord(ev_join, s_side);

    // ---- main stream: weight prep + gemm1 (all rows) ----
    prep_w1t_kernel<<<(IN_F * HID_F + 255) / 256, 256>>>(w1);
    prep_w2t_kernel<<<(HID_F * N_CLS + 255) / 256, 256>>>(w2);
    gemm_pipe_kernel<HID_F, IN_F>
        <<<(N_NODES + 127) / 128, 256, SMEM_PIPE(HID_F)>>>(x, w1h, w1l, b1, h1, 0, N_NODES);
    cudaEventRecord(ev_g1, 0);

    // ---- layer-1 aggregation + layer-2 projection, split in halves ----
    // half 0 on main stream (needs CSR join + h1)
    cudaStreamWaitEvent(0, ev_join, 0);
    spmm1_warp_kernel<<<HALF_N / 8, 256>>>(h1, h2, 0);
    gemm_pipe_kernel<N_CLS, HID_F>
        <<<HALF_N / 128, 256, SMEM_PIPE(N_CLS)>>>(h2, w2h, w2l, b2, h3, 0, HALF_N);

    // half 1 on side stream (CSR already ordered there; wait for gemm1)
    cudaStreamWaitEvent(s_side, ev_g1, 0);
    spmm1_warp_kernel<<<(N_NODES - HALF_N) / 8, 256, 0, s_side>>>(h1, h2, HALF_N);
    gemm_pipe_kernel<N_CLS, HID_F>
        <<<(N_NODES - HALF_N + 127) / 128, 256, SMEM_PIPE(N_CLS), s_side>>>(
            h2, w2h, w2l, b2, h3, HALF_N, N_NODES);
    cudaEventRecord(ev_l2, s_side);

    // ---- final aggregation (needs all h3) ----
    cudaStreamWaitEvent(0, ev_l2, 0);
    spmm2_warp_kernel<<<(N_NODES + 7) / 8, 256>>>(h3, out);
}